// round 8
// baseline (speedup 1.0000x reference)
#include <cuda_runtime.h>
#include <cuda_bf16.h>
#include <cstdint>

#define D 128
#define NSEG 50000

// ---------------- device scratch ----------------
__device__ __align__(16) float g_segsum[NSEG * D];
__device__ __align__(16) float g_cnt[NSEG];
// transposed weights Wt[n][k] = W[k][n], bf16 hi/lo split, 4 matrices
__device__ __align__(16) __nv_bfloat16 g_Whi[4][D * D];
__device__ __align__(16) __nv_bfloat16 g_Wlo[4][D * D];

// ---------------- smem layouts (bytes) ----------------
#define SROW 272u
// phi (128-row tile, 1024 threads, persistent)
#define SW_HI 0u
#define SW_LO 34816u
#define SA_HI 69632u
#define SA_LO 104448u
#define STAGE 139264u      // fp32 A staging, 65536 B
#define PBIAS 204800u
#define PSEG0 205312u
#define PSEG1 205824u
#define PHI_SMEM 206336u
// rho (64-row tile, 512 threads, 2 CTAs/SM)
#define R_SAHI 69632u
#define R_SALO 87040u
#define R_BIAS 104448u
#define R_CNT  105984u
#define RHO_SMEM 106496u

__device__ __forceinline__ uint32_t smem_u32(const void* p) {
    return (uint32_t)__cvta_generic_to_shared(p);
}

#define LDSM_X4(r0, r1, r2, r3, addr)                                         \
    asm volatile("ldmatrix.sync.aligned.m8n8.x4.shared.b16 {%0,%1,%2,%3}, [%4];" \
                 : "=r"(r0), "=r"(r1), "=r"(r2), "=r"(r3) : "r"(addr))

#define MMA16816(d, a, b0, b1)                                                \
    asm volatile("mma.sync.aligned.m16n8k16.row.col.f32.bf16.bf16.f32 "       \
                 "{%0,%1,%2,%3},{%4,%5,%6,%7},{%8,%9},{%0,%1,%2,%3};"         \
                 : "+f"((d)[0]), "+f"((d)[1]), "+f"((d)[2]), "+f"((d)[3])     \
                 : "r"((a)[0]), "r"((a)[1]), "r"((a)[2]), "r"((a)[3]),        \
                   "r"(b0), "r"(b1))

__device__ __forceinline__ uint32_t pack_bf2(float x, float y) {
    __nv_bfloat162 t = __floats2bfloat162_rn(x, y);
    return *(uint32_t*)&t;
}
__device__ __forceinline__ void cp16(uint32_t dst, const void* src, int bytes) {
    asm volatile("cp.async.cg.shared.global [%0], [%1], 16, %2;"
                 :: "r"(dst), "l"(src), "r"(bytes) : "memory");
}
__device__ __forceinline__ void cp_commit() {
    asm volatile("cp.async.commit_group;" ::: "memory");
}
__device__ __forceinline__ void cp_wait0() {
    asm volatile("cp.async.wait_group 0;" ::: "memory");
}

// ---------------------------------------------------------------------------
__global__ void prep_kernel(const float* __restrict__ W0, const float* __restrict__ W1,
                            const float* __restrict__ W2, const float* __restrict__ W3) {
    int i = blockIdx.x * blockDim.x + threadIdx.x;
    if (i >= 4 * D * D) return;
    const float* Ws[4] = {W0, W1, W2, W3};
    int mat = i >> 14;
    int e = i & (D * D - 1);
    int n = e >> 7, k = e & (D - 1);
    float w = Ws[mat][k * D + n];
    __nv_bfloat16 hi = __float2bfloat16_rn(w);
    float lo = w - __bfloat162float(hi);
    g_Whi[mat][n * D + k] = hi;
    g_Wlo[mat][n * D + k] = __float2bfloat16_rn(lo);
}

__global__ void zero_kernel() {
    int i = blockIdx.x * blockDim.x + threadIdx.x;
    float4 z = make_float4(0.f, 0.f, 0.f, 0.f);
    if (i < NSEG * D / 4) ((float4*)g_segsum)[i] = z;
    if (i < NSEG / 4) ((float4*)g_cnt)[i] = z;
}

// ---------------------------------------------------------------------------
template <int NTHR>
__device__ __forceinline__ void load_W_pair(char* smem,
                                            const __nv_bfloat16* __restrict__ Whi,
                                            const __nv_bfloat16* __restrict__ Wlo,
                                            int tid) {
    for (int idx = tid; idx < 128 * 16; idx += NTHR) {
        int r = idx >> 4, ch = idx & 15;
        uint32_t off = (uint32_t)r * SROW + (uint32_t)ch * 16;
        *(uint4*)(smem + SW_HI + off) = *(const uint4*)(Whi + r * D + ch * 8);
        *(uint4*)(smem + SW_LO + off) = *(const uint4*)(Wlo + r * D + ch * 8);
    }
}

// software-pipelined 3-term pass: acc += Ahi*Whi + Alo*Whi + Ahi*Wlo.
// Per warp: 16 rows x 32 cols (acc[4][4]); addresses are lane-resolved by caller.
__device__ __forceinline__ void gemm_pass3(uint32_t aHi, uint32_t aLo,
                                           uint32_t bHi, uint32_t bLo,
                                           float (*acc)[4]) {
    uint32_t A0[4], A1[4], W0[4], V0[4];
    LDSM_X4(A0[0], A0[1], A0[2], A0[3], aHi);
    LDSM_X4(A1[0], A1[1], A1[2], A1[3], aLo);
    LDSM_X4(W0[0], W0[1], W0[2], W0[3], bHi);
    LDSM_X4(V0[0], V0[1], V0[2], V0[3], bLo);
#pragma unroll
    for (int k = 0; k < 8; k++) {
        // prefetch B(k, nb=1)
        uint32_t W1[4], V1[4];
        LDSM_X4(W1[0], W1[1], W1[2], W1[3], bHi + 16u * SROW);
        LDSM_X4(V1[0], V1[1], V1[2], V1[3], bLo + 16u * SROW);
        // MMA nb=0
        MMA16816(acc[0], A0, W0[0], W0[1]);
        MMA16816(acc[1], A0, W0[2], W0[3]);
        MMA16816(acc[0], A1, W0[0], W0[1]);
        MMA16816(acc[1], A1, W0[2], W0[3]);
        MMA16816(acc[0], A0, V0[0], V0[1]);
        MMA16816(acc[1], A0, V0[2], V0[3]);
        // prefetch A(k+1), B(k+1, nb=0)
        uint32_t A0n[4], A1n[4], W0n[4], V0n[4];
        if (k < 7) {
            LDSM_X4(A0n[0], A0n[1], A0n[2], A0n[3], aHi + 32);
            LDSM_X4(A1n[0], A1n[1], A1n[2], A1n[3], aLo + 32);
            LDSM_X4(W0n[0], W0n[1], W0n[2], W0n[3], bHi + 32);
            LDSM_X4(V0n[0], V0n[1], V0n[2], V0n[3], bLo + 32);
        }
        // MMA nb=1
        MMA16816(acc[2], A0, W1[0], W1[1]);
        MMA16816(acc[3], A0, W1[2], W1[3]);
        MMA16816(acc[2], A1, W1[0], W1[1]);
        MMA16816(acc[3], A1, W1[2], W1[3]);
        MMA16816(acc[2], A0, V1[0], V1[1]);
        MMA16816(acc[3], A0, V1[2], V1[3]);
        // rotate
        if (k < 7) {
#pragma unroll
            for (int i = 0; i < 4; i++) {
                A0[i] = A0n[i]; A1[i] = A1n[i];
                W0[i] = W0n[i]; V0[i] = V0n[i];
            }
            aHi += 32; aLo += 32; bHi += 32; bLo += 32;
        }
    }
}

// lane-resolved operand addresses (A tile base saHi/saLo, warp tile wm/wn)
__device__ __forceinline__ void mma_addrs(uint32_t sbase, uint32_t saHi, uint32_t saLo,
                                          int wm, int wn, int lane,
                                          uint32_t& aHi, uint32_t& aLo,
                                          uint32_t& bHi, uint32_t& bLo) {
    const uint32_t aRow = (uint32_t)(wm * 16 + (lane & 15));
    const uint32_t aColB = (uint32_t)((lane >> 4) * 16);
    aHi = sbase + saHi + aRow * SROW + aColB;
    aLo = sbase + saLo + aRow * SROW + aColB;
    const uint32_t bRow = (uint32_t)((lane & 7) + ((lane & 16) ? 8 : 0));
    const uint32_t bColB = (uint32_t)(((lane & 8) ? 8 : 0) * 2);
    bHi = sbase + SW_HI + (bRow + (uint32_t)wn * 32u) * SROW + bColB;
    bLo = sbase + SW_LO + (bRow + (uint32_t)wn * 32u) * SROW + bColB;
}

// fragments (+bias, opt relu, opt zero-empty) back to A smem as bf16 hi/lo
__device__ __forceinline__ void frag_store_A(char* smem, uint32_t saHi, uint32_t saLo,
                                             float (*acc)[4],
                                             const float* bias, const float* sCnt,
                                             bool relu, bool zeroE,
                                             int wm, int wn, int lane) {
    const int grp = lane >> 2, qp = lane & 3;
    const int rA = wm * 16 + grp;
    bool z0 = zeroE && (sCnt[rA] <= 0.f);
    bool z1 = zeroE && (sCnt[rA + 8] <= 0.f);
#pragma unroll
    for (int nt = 0; nt < 4; nt++) {
        int c = wn * 32 + nt * 8 + qp * 2;
        float b0 = bias[c], b1 = bias[c + 1];
        float x0 = acc[nt][0] + b0, y0 = acc[nt][1] + b1;
        float x1 = acc[nt][2] + b0, y1 = acc[nt][3] + b1;
        if (relu) {
            x0 = fmaxf(x0, 0.f); y0 = fmaxf(y0, 0.f);
            x1 = fmaxf(x1, 0.f); y1 = fmaxf(y1, 0.f);
        }
        if (z0) { x0 = 0.f; y0 = 0.f; }
        if (z1) { x1 = 0.f; y1 = 0.f; }
        float hx0 = __bfloat162float(__float2bfloat16_rn(x0));
        float hy0 = __bfloat162float(__float2bfloat16_rn(y0));
        float hx1 = __bfloat162float(__float2bfloat16_rn(x1));
        float hy1 = __bfloat162float(__float2bfloat16_rn(y1));
        uint32_t o0 = (uint32_t)rA * SROW + (uint32_t)c * 2;
        uint32_t o1 = (uint32_t)(rA + 8) * SROW + (uint32_t)c * 2;
        *(uint32_t*)(smem + saHi + o0) = pack_bf2(hx0, hy0);
        *(uint32_t*)(smem + saLo + o0) = pack_bf2(x0 - hx0, y0 - hy0);
        *(uint32_t*)(smem + saHi + o1) = pack_bf2(hx1, hy1);
        *(uint32_t*)(smem + saLo + o1) = pack_bf2(x1 - hx1, y1 - hy1);
    }
}

// ---------------------------------------------------------------------------
// PERSISTENT phi kernel (1024 threads, 128-row tiles): W1 hi/lo resident.
// ---------------------------------------------------------------------------
__global__ __launch_bounds__(1024, 1) void phi_seg_kernel(
    const float* __restrict__ ins, const int* __restrict__ batch,
    const __nv_bfloat16* __restrict__ Whi, const __nv_bfloat16* __restrict__ Wlo,
    const float* __restrict__ bias, int nrows, int ntiles)
{
    extern __shared__ __align__(16) char smem[];
    const uint32_t sbase = smem_u32(smem);
    const int tid = threadIdx.x;
    const int wid = tid >> 5, lane = tid & 31;
    const int wm = wid & 7, wn = wid >> 3;

    // prologue prefetch of first tile
    {
        int t = blockIdx.x;
        if (t < ntiles) {
            long long row0 = (long long)t * 128;
            for (int idx = tid; idx < 4096; idx += 1024) {
                int r = idx >> 5, c = idx & 31;
                long long gr = row0 + r;
                cp16(sbase + STAGE + (uint32_t)idx * 16u,
                     ins + gr * D + c * 4, (gr < nrows) ? 16 : 0);
            }
            if (tid < 32) {
                long long r0 = row0 + tid * 4;
                long long rem = (long long)nrows - r0;
                int sz = rem >= 4 ? 16 : (rem > 0 ? (int)rem * 4 : 0);
                cp16(sbase + PSEG0 + (uint32_t)tid * 16u, batch + r0, sz);
            }
        }
        cp_commit();
    }
    load_W_pair<1024>(smem, Whi, Wlo, tid);
    if (tid < D) ((float*)(smem + PBIAS))[tid] = bias[tid];

    uint32_t aHi0, aLo0, bHi0, bLo0;
    mma_addrs(sbase, SA_HI, SA_LO, wm, wn, lane, aHi0, aLo0, bHi0, bLo0);

    int buf = 0;
    for (int t = blockIdx.x; t < ntiles; t += gridDim.x) {
        cp_wait0();
        __syncthreads();
        // convert staged fp32 -> bf16 hi/lo
        for (int idx = tid; idx < 4096; idx += 1024) {
            int r = idx >> 5, c4 = idx & 31;
            float4 v = *(const float4*)(smem + STAGE + (uint32_t)r * 512u + (uint32_t)c4 * 16u);
            float hx = __bfloat162float(__float2bfloat16_rn(v.x));
            float hy = __bfloat162float(__float2bfloat16_rn(v.y));
            float hz = __bfloat162float(__float2bfloat16_rn(v.z));
            float hw = __bfloat162float(__float2bfloat16_rn(v.w));
            uint32_t off = (uint32_t)r * SROW + (uint32_t)c4 * 8;
            *(uint2*)(smem + SA_HI + off) = make_uint2(pack_bf2(hx, hy), pack_bf2(hz, hw));
            *(uint2*)(smem + SA_LO + off) =
                make_uint2(pack_bf2(v.x - hx, v.y - hy), pack_bf2(v.z - hz, v.w - hw));
        }
        __syncthreads();   // stage free -> prefetch next tile
        {
            int nt_ = t + gridDim.x;
            if (nt_ < ntiles) {
                long long row0n = (long long)nt_ * 128;
                for (int idx = tid; idx < 4096; idx += 1024) {
                    int r = idx >> 5, c = idx & 31;
                    long long gr = row0n + r;
                    cp16(sbase + STAGE + (uint32_t)idx * 16u,
                         ins + gr * D + c * 4, (gr < nrows) ? 16 : 0);
                }
                if (tid < 32) {
                    long long r0 = row0n + tid * 4;
                    long long rem = (long long)nrows - r0;
                    int sz = rem >= 4 ? 16 : (rem > 0 ? (int)rem * 4 : 0);
                    cp16(sbase + (buf ? PSEG0 : PSEG1) + (uint32_t)tid * 16u,
                         batch + r0, sz);
                }
            }
            cp_commit();
        }

        float acc[4][4];
#pragma unroll
        for (int i = 0; i < 4; i++)
#pragma unroll
            for (int j = 0; j < 4; j++) acc[i][j] = 0.f;
        gemm_pass3(aHi0, aLo0, bHi0, bLo0, acc);
        __syncthreads();   // A buffers free

        // h = relu(acc + b) into sH (reuses A region)
        float* sH = (float*)(smem + SA_HI);
        const float* sB = (const float*)(smem + PBIAS);
        {
            const int grp = lane >> 2, qp = lane & 3;
            const int rA = wm * 16 + grp;
#pragma unroll
            for (int nt = 0; nt < 4; nt++) {
                int c = wn * 32 + nt * 8 + qp * 2;
                float b0 = sB[c], b1 = sB[c + 1];
                *(float2*)(sH + rA * 128 + c) =
                    make_float2(fmaxf(acc[nt][0] + b0, 0.f), fmaxf(acc[nt][1] + b1, 0.f));
                *(float2*)(sH + (rA + 8) * 128 + c) =
                    make_float2(fmaxf(acc[nt][2] + b0, 0.f), fmaxf(acc[nt][3] + b1, 0.f));
            }
        }
        __syncthreads();

        // segment reduce: preload 16 h values (independent LDS), then run scan
        const int* sSeg = (const int*)(smem + (buf ? PSEG1 : PSEG0));
        const int row0 = t * 128;
        const int col = tid & (D - 1);
        const int rbeg = (tid >> 7) * 16;
        float hv[16];
#pragma unroll
        for (int r = 0; r < 16; r++) hv[r] = sH[(rbeg + r) * 128 + col];
        int cur = (row0 + rbeg < nrows) ? sSeg[rbeg] : -1;
        float run = 0.f, cnt = 0.f;
#pragma unroll
        for (int r = 0; r < 16; r++) {
            int s = (row0 + rbeg + r < nrows) ? sSeg[rbeg + r] : -1;
            if (s != cur) {
                if (cur >= 0) {
                    atomicAdd(&g_segsum[(size_t)cur * D + col], run);
                    if (col == 0) atomicAdd(&g_cnt[cur], cnt);
                }
                cur = s; run = 0.f; cnt = 0.f;
            }
            run += hv[r];
            cnt += 1.f;
        }
        if (cur >= 0) {
            atomicAdd(&g_segsum[(size_t)cur * D + col], run);
            if (col == 0) atomicAdd(&g_cnt[cur], cnt);
        }
        __syncthreads();   // sH reads done before next convert overwrites
        buf ^= 1;
    }
}

// ---------------------------------------------------------------------------
// fused small path: 64-row tiles, 512 threads, 2 CTAs/SM.
// u = mean@phiW2+b2 (zero-empty); v = relu(u@rhoW1+rb1); out = v@rhoW2+rb2.
// ---------------------------------------------------------------------------
__global__ __launch_bounds__(512, 2) void rho_fused_kernel(
    const __nv_bfloat16* __restrict__ W2hi, const __nv_bfloat16* __restrict__ W2lo,
    const __nv_bfloat16* __restrict__ R1hi, const __nv_bfloat16* __restrict__ R1lo,
    const __nv_bfloat16* __restrict__ R2hi, const __nv_bfloat16* __restrict__ R2lo,
    const float* __restrict__ b2, const float* __restrict__ rb1,
    const float* __restrict__ rb2, float* __restrict__ outp, int nrows)
{
    extern __shared__ __align__(16) char smem[];
    const uint32_t sbase = smem_u32(smem);
    const int tid = threadIdx.x;
    const int wid = tid >> 5, lane = tid & 31;
    const int wm = wid & 3, wn = wid >> 2;      // 4 M-tiles x 4 N-quarters
    const int row0 = blockIdx.x * 64;

    float* sB = (float*)(smem + R_BIAS);
    float* sCnt = (float*)(smem + R_CNT);
    if (tid < D) {
        sB[tid] = b2[tid];
        sB[128 + tid] = rb1[tid];
        sB[256 + tid] = rb2[tid];
    }
    if (tid < 64) {
        int gr = row0 + tid;
        sCnt[tid] = (gr < nrows) ? g_cnt[gr] : 0.f;
    }
    load_W_pair<512>(smem, W2hi, W2lo, tid);
    __syncthreads();

    // A tile: mean = segsum / max(cnt,1), split hi/lo (64 rows)
    for (int idx = tid; idx < 64 * 32; idx += 512) {
        int r = idx >> 5, c4 = idx & 31;
        float4 v = make_float4(0.f, 0.f, 0.f, 0.f);
        int gr = row0 + r;
        if (gr < nrows) {
            v = *(const float4*)(g_segsum + (size_t)gr * D + c4 * 4);
            float s = 1.f / fmaxf(sCnt[r], 1.f);
            v.x *= s; v.y *= s; v.z *= s; v.w *= s;
        }
        float hx = __bfloat162float(__float2bfloat16_rn(v.x));
        float hy = __bfloat162float(__float2bfloat16_rn(v.y));
        float hz = __bfloat162float(__float2bfloat16_rn(v.z));
        float hw = __bfloat162float(__float2bfloat16_rn(v.w));
        uint32_t off = (uint32_t)r * SROW + (uint32_t)c4 * 8;
        *(uint2*)(smem + R_SAHI + off) = make_uint2(pack_bf2(hx, hy), pack_bf2(hz, hw));
        *(uint2*)(smem + R_SALO + off) =
            make_uint2(pack_bf2(v.x - hx, v.y - hy), pack_bf2(v.z - hz, v.w - hw));
    }
    __syncthreads();

    uint32_t aHi0, aLo0, bHi0, bLo0;
    mma_addrs(sbase, R_SAHI, R_SALO, wm, wn, lane, aHi0, aLo0, bHi0, bLo0);

    float acc[4][4];
    // ---- stage 1: u = mean@phiW2 + b2 (zero empty rows) ----
#pragma unroll
    for (int i = 0; i < 4; i++)
#pragma unroll
        for (int j = 0; j < 4; j++) acc[i][j] = 0.f;
    gemm_pass3(aHi0, aLo0, bHi0, bLo0, acc);
    __syncthreads();
    frag_store_A(smem, R_SAHI, R_SALO, acc, sB, sCnt, false, true, wm, wn, lane);
    load_W_pair<512>(smem, R1hi, R1lo, tid);
    __syncthreads();

    // ---- stage 2: v = relu(u@rhoW1 + rb1) ----
#pragma unroll
    for (int i = 0; i < 4; i++)
#pragma unroll
        for (int j = 0; j < 4; j++) acc[i][j] = 0.f;
    gemm_pass3(aHi0, aLo0, bHi0, bLo0, acc);
    __syncthreads();
    frag_store_A(smem, R_SAHI, R_SALO, acc, sB + 128, sCnt, true, false, wm, wn, lane);
    load_W_pair<512>(smem, R2hi, R2lo, tid);
    __syncthreads();

    // ---- stage 3: out = v@rhoW2 + rb2 ----
#pragma unroll
    for (int i = 0; i < 4; i++)
#pragma unroll
        for (int j = 0; j < 4; j++) acc[i][j] = 0.f;
    gemm_pass3(aHi0, aLo0, bHi0, bLo0, acc);
    {
        const int grp = lane >> 2, qp = lane & 3;
        const int rA = wm * 16 + grp;
        int gr0 = row0 + rA, gr1 = row0 + rA + 8;
#pragma unroll
        for (int nt = 0; nt < 4; nt++) {
            int c = wn * 32 + nt * 8 + qp * 2;
            float b0 = sB[256 + c], b1 = sB[256 + c + 1];
            if (gr0 < nrows)
                *(float2*)(outp + (size_t)gr0 * D + c) =
                    make_float2(acc[nt][0] + b0, acc[nt][1] + b1);
            if (gr1 < nrows)
                *(float2*)(outp + (size_t)gr1 * D + c) =
                    make_float2(acc[nt][2] + b0, acc[nt][3] + b1);
        }
    }
}

// ---------------------------------------------------------------------------
extern "C" void kernel_launch(void* const* d_in, const int* in_sizes, int n_in,
                              void* d_out, int out_size)
{
    const float* ins    = (const float*)d_in[0];
    const int*   batch  = (const int*)d_in[1];
    const float* phi_W1 = (const float*)d_in[3];
    const float* phi_b1 = (const float*)d_in[4];
    const float* phi_W2 = (const float*)d_in[5];
    const float* phi_b2 = (const float*)d_in[6];
    const float* rho_W1 = (const float*)d_in[7];
    const float* rho_b1 = (const float*)d_in[8];
    const float* rho_W2 = (const float*)d_in[9];
    const float* rho_b2 = (const float*)d_in[10];
    float* out = (float*)d_out;

    const int N = in_sizes[0] / D;
    const int ntiles = (N + 127) / 128;

    cudaFuncSetAttribute(phi_seg_kernel, cudaFuncAttributeMaxDynamicSharedMemorySize, PHI_SMEM);
    cudaFuncSetAttribute(rho_fused_kernel, cudaFuncAttributeMaxDynamicSharedMemorySize, RHO_SMEM);

    void *p_whi = nullptr, *p_wlo = nullptr;
    cudaGetSymbolAddress(&p_whi, g_Whi);
    cudaGetSymbolAddress(&p_wlo, g_Wlo);
    const __nv_bfloat16* Whi = (const __nv_bfloat16*)p_whi;
    const __nv_bfloat16* Wlo = (const __nv_bfloat16*)p_wlo;

    int zgrid = (NSEG * D / 4 + 255) / 256;
    zero_kernel<<<zgrid, 256>>>();
    prep_kernel<<<(4 * D * D + 255) / 256, 256>>>(phi_W1, phi_W2, rho_W1, rho_W2);

    int gphi = 148;
    if (gphi > ntiles) gphi = ntiles;
    phi_seg_kernel<<<gphi, 1024, PHI_SMEM>>>(ins, batch,
        Whi + 0 * D * D, Wlo + 0 * D * D, phi_b1, N, ntiles);

    int g2 = (NSEG + 63) / 64;
    rho_fused_kernel<<<g2, 512, RHO_SMEM>>>(
        Whi + 1 * D * D, Wlo + 1 * D * D,
        Whi + 2 * D * D, Wlo + 2 * D * D,
        Whi + 3 * D * D, Wlo + 3 * D * D,
        phi_b2, rho_b1, rho_b2, out, NSEG);
}

// round 9
// speedup vs baseline: 1.0229x; 1.0229x over previous
#include <cuda_runtime.h>
#include <cuda_bf16.h>
#include <cstdint>

#define D 128
#define NSEG 50000

// ---------------- device scratch ----------------
__device__ __align__(16) float g_segsum[NSEG * D];
__device__ __align__(16) float g_cnt[NSEG];
// transposed weights Wt[n][k] = W[k][n], bf16 hi/lo split, 4 matrices
__device__ __align__(16) __nv_bfloat16 g_Whi[4][D * D];
__device__ __align__(16) __nv_bfloat16 g_Wlo[4][D * D];

// ---------------- smem layouts (bytes) ----------------
#define SROW 272u
#define SW_HI 0u
#define SW_LO 34816u
#define SA_HI 69632u
#define SA_LO 104448u
// phi persistent extras
#define STAGE 139264u      // fp32 A staging, 65536 B
#define PBIAS 204800u
#define PSEG0 205312u
#define PSEG1 205824u
#define PHI_SMEM 206336u
// rho extras
#define RBIAS 139264u      // 3 x 512 B
#define RCNT  140800u      // 512 B
#define RHO_SMEM 141312u

__device__ __forceinline__ uint32_t smem_u32(const void* p) {
    return (uint32_t)__cvta_generic_to_shared(p);
}

#define LDSM_X4(r, addr)                                                      \
    asm volatile("ldmatrix.sync.aligned.m8n8.x4.shared.b16 {%0,%1,%2,%3}, [%4];" \
                 : "=r"((r)[0]), "=r"((r)[1]), "=r"((r)[2]), "=r"((r)[3])     \
                 : "r"(addr))

#define MMA16816(d, a, b0, b1)                                                \
    asm volatile("mma.sync.aligned.m16n8k16.row.col.f32.bf16.bf16.f32 "       \
                 "{%0,%1,%2,%3},{%4,%5,%6,%7},{%8,%9},{%0,%1,%2,%3};"         \
                 : "+f"((d)[0]), "+f"((d)[1]), "+f"((d)[2]), "+f"((d)[3])     \
                 : "r"((a)[0]), "r"((a)[1]), "r"((a)[2]), "r"((a)[3]),        \
                   "r"(b0), "r"(b1))

__device__ __forceinline__ uint32_t pack_bf2(float x, float y) {
    __nv_bfloat162 t = __floats2bfloat162_rn(x, y);
    return *(uint32_t*)&t;
}
__device__ __forceinline__ void cp16(uint32_t dst, const void* src, int bytes) {
    asm volatile("cp.async.cg.shared.global [%0], [%1], 16, %2;"
                 :: "r"(dst), "l"(src), "r"(bytes) : "memory");
}
__device__ __forceinline__ void cp_commit() {
    asm volatile("cp.async.commit_group;" ::: "memory");
}
__device__ __forceinline__ void cp_wait0() {
    asm volatile("cp.async.wait_group 0;" ::: "memory");
}

// ---------------------------------------------------------------------------
__global__ void prep_kernel(const float* __restrict__ W0, const float* __restrict__ W1,
                            const float* __restrict__ W2, const float* __restrict__ W3) {
    int i = blockIdx.x * blockDim.x + threadIdx.x;
    if (i >= 4 * D * D) return;
    const float* Ws[4] = {W0, W1, W2, W3};
    int mat = i >> 14;
    int e = i & (D * D - 1);
    int n = e >> 7, k = e & (D - 1);
    float w = Ws[mat][k * D + n];
    __nv_bfloat16 hi = __float2bfloat16_rn(w);
    float lo = w - __bfloat162float(hi);
    g_Whi[mat][n * D + k] = hi;
    g_Wlo[mat][n * D + k] = __float2bfloat16_rn(lo);
}

__global__ void zero_kernel() {
    int i = blockIdx.x * blockDim.x + threadIdx.x;
    float4 z = make_float4(0.f, 0.f, 0.f, 0.f);
    if (i < NSEG * D / 4) ((float4*)g_segsum)[i] = z;
    if (i < NSEG / 4) ((float4*)g_cnt)[i] = z;
}

// ---------------------------------------------------------------------------
template <int NTHR>
__device__ __forceinline__ void load_W_pair(char* smem,
                                            const __nv_bfloat16* __restrict__ Whi,
                                            const __nv_bfloat16* __restrict__ Wlo,
                                            int tid) {
    for (int idx = tid; idx < 128 * 16; idx += NTHR) {
        int r = idx >> 4, ch = idx & 15;
        uint32_t off = (uint32_t)r * SROW + (uint32_t)ch * 16;
        *(uint4*)(smem + SW_HI + off) = *(const uint4*)(Whi + r * D + ch * 8);
        *(uint4*)(smem + SW_LO + off) = *(const uint4*)(Wlo + r * D + ch * 8);
    }
}

// ======== 16x32 warp tile, pipelined (rho: 32 warps over 128x128) ========
__device__ __forceinline__ void gemm_pass3_16(uint32_t aHi, uint32_t aLo,
                                              uint32_t bHi, uint32_t bLo,
                                              float (*acc)[4]) {
    uint32_t A0[4], A1[4], W0[4], V0[4];
    LDSM_X4(A0, aHi);
    LDSM_X4(A1, aLo);
    LDSM_X4(W0, bHi);
    LDSM_X4(V0, bLo);
#pragma unroll
    for (int k = 0; k < 8; k++) {
        uint32_t W1[4], V1[4];
        LDSM_X4(W1, bHi + 16u * SROW);
        LDSM_X4(V1, bLo + 16u * SROW);
        MMA16816(acc[0], A0, W0[0], W0[1]);
        MMA16816(acc[1], A0, W0[2], W0[3]);
        MMA16816(acc[0], A1, W0[0], W0[1]);
        MMA16816(acc[1], A1, W0[2], W0[3]);
        MMA16816(acc[0], A0, V0[0], V0[1]);
        MMA16816(acc[1], A0, V0[2], V0[3]);
        uint32_t A0n[4], A1n[4], W0n[4], V0n[4];
        if (k < 7) {
            LDSM_X4(A0n, aHi + 32);
            LDSM_X4(A1n, aLo + 32);
            LDSM_X4(W0n, bHi + 32);
            LDSM_X4(V0n, bLo + 32);
        }
        MMA16816(acc[2], A0, W1[0], W1[1]);
        MMA16816(acc[3], A0, W1[2], W1[3]);
        MMA16816(acc[2], A1, W1[0], W1[1]);
        MMA16816(acc[3], A1, W1[2], W1[3]);
        MMA16816(acc[2], A0, V1[0], V1[1]);
        MMA16816(acc[3], A0, V1[2], V1[3]);
        if (k < 7) {
#pragma unroll
            for (int i = 0; i < 4; i++) {
                A0[i] = A0n[i]; A1[i] = A1n[i];
                W0[i] = W0n[i]; V0[i] = V0n[i];
            }
            aHi += 32; aLo += 32; bHi += 32; bLo += 32;
        }
    }
}

// ======== 32x32 warp tile, pipelined (phi: 16 warps over 128x128) ========
// acc[2][4][4]: [m-frag][n-frag][quad]
__device__ __forceinline__ void gemm_pass3_32(uint32_t aHi, uint32_t aLo,
                                              uint32_t bHi, uint32_t bLo,
                                              float (*acc)[4][4]) {
    uint32_t AH0[4], AH1[4], AL0[4], AL1[4], WH0[4], WH1[4], WL0[4], WL1[4];
    LDSM_X4(AH0, aHi);
    LDSM_X4(AH1, aHi + 16u * SROW);
    LDSM_X4(AL0, aLo);
    LDSM_X4(AL1, aLo + 16u * SROW);
    LDSM_X4(WH0, bHi);
    LDSM_X4(WH1, bHi + 16u * SROW);
    LDSM_X4(WL0, bLo);
    LDSM_X4(WL1, bLo + 16u * SROW);
#pragma unroll
    for (int k = 0; k < 8; k++) {
        uint32_t AH0n[4], AH1n[4], AL0n[4], AL1n[4];
        uint32_t WH0n[4], WH1n[4], WL0n[4], WL1n[4];
        if (k < 7) {
            LDSM_X4(AH0n, aHi + 32);
            LDSM_X4(AH1n, aHi + 16u * SROW + 32);
            LDSM_X4(WH0n, bHi + 32);
            LDSM_X4(WH1n, bHi + 16u * SROW + 32);
        }
        // hi*hi
        MMA16816(acc[0][0], AH0, WH0[0], WH0[1]);
        MMA16816(acc[0][1], AH0, WH0[2], WH0[3]);
        MMA16816(acc[0][2], AH0, WH1[0], WH1[1]);
        MMA16816(acc[0][3], AH0, WH1[2], WH1[3]);
        MMA16816(acc[1][0], AH1, WH0[0], WH0[1]);
        MMA16816(acc[1][1], AH1, WH0[2], WH0[3]);
        MMA16816(acc[1][2], AH1, WH1[0], WH1[1]);
        MMA16816(acc[1][3], AH1, WH1[2], WH1[3]);
        if (k < 7) {
            LDSM_X4(AL0n, aLo + 32);
            LDSM_X4(AL1n, aLo + 16u * SROW + 32);
            LDSM_X4(WL0n, bLo + 32);
            LDSM_X4(WL1n, bLo + 16u * SROW + 32);
        }
        // lo*hi
        MMA16816(acc[0][0], AL0, WH0[0], WH0[1]);
        MMA16816(acc[0][1], AL0, WH0[2], WH0[3]);
        MMA16816(acc[0][2], AL0, WH1[0], WH1[1]);
        MMA16816(acc[0][3], AL0, WH1[2], WH1[3]);
        MMA16816(acc[1][0], AL1, WH0[0], WH0[1]);
        MMA16816(acc[1][1], AL1, WH0[2], WH0[3]);
        MMA16816(acc[1][2], AL1, WH1[0], WH1[1]);
        MMA16816(acc[1][3], AL1, WH1[2], WH1[3]);
        // hi*lo
        MMA16816(acc[0][0], AH0, WL0[0], WL0[1]);
        MMA16816(acc[0][1], AH0, WL0[2], WL0[3]);
        MMA16816(acc[0][2], AH0, WL1[0], WL1[1]);
        MMA16816(acc[0][3], AH0, WL1[2], WL1[3]);
        MMA16816(acc[1][0], AH1, WL0[0], WL0[1]);
        MMA16816(acc[1][1], AH1, WL0[2], WL0[3]);
        MMA16816(acc[1][2], AH1, WL1[0], WL1[1]);
        MMA16816(acc[1][3], AH1, WL1[2], WL1[3]);
        if (k < 7) {
#pragma unroll
            for (int i = 0; i < 4; i++) {
                AH0[i] = AH0n[i]; AH1[i] = AH1n[i];
                AL0[i] = AL0n[i]; AL1[i] = AL1n[i];
                WH0[i] = WH0n[i]; WH1[i] = WH1n[i];
                WL0[i] = WL0n[i]; WL1[i] = WL1n[i];
            }
            aHi += 32; aLo += 32; bHi += 32; bLo += 32;
        }
    }
}

// fragments (+bias, opt relu, opt zero-empty) back to A smem as bf16 hi/lo
// (rho 16x32 tiles)
__device__ __forceinline__ void frag_store_A(char* smem, float (*acc)[4],
                                             const float* bias, const float* sCnt,
                                             bool relu, bool zeroE,
                                             int wm, int wn, int lane) {
    const int grp = lane >> 2, qp = lane & 3;
    const int rA = wm * 16 + grp;
    bool z0 = zeroE && (sCnt[rA] <= 0.f);
    bool z1 = zeroE && (sCnt[rA + 8] <= 0.f);
#pragma unroll
    for (int nt = 0; nt < 4; nt++) {
        int c = wn * 32 + nt * 8 + qp * 2;
        float b0 = bias[c], b1 = bias[c + 1];
        float x0 = acc[nt][0] + b0, y0 = acc[nt][1] + b1;
        float x1 = acc[nt][2] + b0, y1 = acc[nt][3] + b1;
        if (relu) {
            x0 = fmaxf(x0, 0.f); y0 = fmaxf(y0, 0.f);
            x1 = fmaxf(x1, 0.f); y1 = fmaxf(y1, 0.f);
        }
        if (z0) { x0 = 0.f; y0 = 0.f; }
        if (z1) { x1 = 0.f; y1 = 0.f; }
        float hx0 = __bfloat162float(__float2bfloat16_rn(x0));
        float hy0 = __bfloat162float(__float2bfloat16_rn(y0));
        float hx1 = __bfloat162float(__float2bfloat16_rn(x1));
        float hy1 = __bfloat162float(__float2bfloat16_rn(y1));
        uint32_t o0 = (uint32_t)rA * SROW + (uint32_t)c * 2;
        uint32_t o1 = (uint32_t)(rA + 8) * SROW + (uint32_t)c * 2;
        *(uint32_t*)(smem + SA_HI + o0) = pack_bf2(hx0, hy0);
        *(uint32_t*)(smem + SA_LO + o0) = pack_bf2(x0 - hx0, y0 - hy0);
        *(uint32_t*)(smem + SA_HI + o1) = pack_bf2(hx1, hy1);
        *(uint32_t*)(smem + SA_LO + o1) = pack_bf2(x1 - hx1, y1 - hy1);
    }
}

// ---------------------------------------------------------------------------
// PERSISTENT phi kernel: 512 threads, 16 warps as 4x4 grid of 32x32 tiles.
// ---------------------------------------------------------------------------
__global__ __launch_bounds__(512, 1) void phi_seg_kernel(
    const float* __restrict__ ins, const int* __restrict__ batch,
    const __nv_bfloat16* __restrict__ Whi, const __nv_bfloat16* __restrict__ Wlo,
    const float* __restrict__ bias, int nrows, int ntiles)
{
    extern __shared__ __align__(16) char smem[];
    const uint32_t sbase = smem_u32(smem);
    const int tid = threadIdx.x;
    const int wid = tid >> 5, lane = tid & 31;
    const int wm = wid & 3, wn = wid >> 2;   // 4 M strips x 4 N strips, 32x32 each

    // prologue prefetch of first tile
    {
        int t = blockIdx.x;
        if (t < ntiles) {
            long long row0 = (long long)t * 128;
            for (int idx = tid; idx < 4096; idx += 512) {
                int r = idx >> 5, c = idx & 31;
                long long gr = row0 + r;
                cp16(sbase + STAGE + (uint32_t)idx * 16u,
                     ins + gr * D + c * 4, (gr < nrows) ? 16 : 0);
            }
            if (tid < 32) {
                long long r0 = row0 + tid * 4;
                long long rem = (long long)nrows - r0;
                int sz = rem >= 4 ? 16 : (rem > 0 ? (int)rem * 4 : 0);
                cp16(sbase + PSEG0 + (uint32_t)tid * 16u, batch + r0, sz);
            }
        }
        cp_commit();
    }
    load_W_pair<512>(smem, Whi, Wlo, tid);
    if (tid < D) ((float*)(smem + PBIAS))[tid] = bias[tid];

    // lane-resolved operand base addresses (32x32 tiles)
    const uint32_t aRow = (uint32_t)(wm * 32 + (lane & 15));
    const uint32_t aColB = (uint32_t)((lane >> 4) * 16);
    const uint32_t aHi0 = sbase + SA_HI + aRow * SROW + aColB;
    const uint32_t aLo0 = sbase + SA_LO + aRow * SROW + aColB;
    const uint32_t bRow = (uint32_t)((lane & 7) + ((lane & 16) ? 8 : 0));
    const uint32_t bColB = (uint32_t)(((lane & 8) ? 8 : 0) * 2);
    const uint32_t bHi0 = sbase + SW_HI + (bRow + (uint32_t)wn * 32u) * SROW + bColB;
    const uint32_t bLo0 = sbase + SW_LO + (bRow + (uint32_t)wn * 32u) * SROW + bColB;

    int buf = 0;
    for (int t = blockIdx.x; t < ntiles; t += gridDim.x) {
        cp_wait0();
        __syncthreads();
        // convert staged fp32 -> bf16 hi/lo
        for (int idx = tid; idx < 4096; idx += 512) {
            int r = idx >> 5, c4 = idx & 31;
            float4 v = *(const float4*)(smem + STAGE + (uint32_t)r * 512u + (uint32_t)c4 * 16u);
            float hx = __bfloat162float(__float2bfloat16_rn(v.x));
            float hy = __bfloat162float(__float2bfloat16_rn(v.y));
            float hz = __bfloat162float(__float2bfloat16_rn(v.z));
            float hw = __bfloat162float(__float2bfloat16_rn(v.w));
            uint32_t off = (uint32_t)r * SROW + (uint32_t)c4 * 8;
            *(uint2*)(smem + SA_HI + off) = make_uint2(pack_bf2(hx, hy), pack_bf2(hz, hw));
            *(uint2*)(smem + SA_LO + off) =
                make_uint2(pack_bf2(v.x - hx, v.y - hy), pack_bf2(v.z - hz, v.w - hw));
        }
        __syncthreads();   // stage free -> prefetch next tile
        {
            int nt_ = t + gridDim.x;
            if (nt_ < ntiles) {
                long long row0n = (long long)nt_ * 128;
                for (int idx = tid; idx < 4096; idx += 512) {
                    int r = idx >> 5, c = idx & 31;
                    long long gr = row0n + r;
                    cp16(sbase + STAGE + (uint32_t)idx * 16u,
                         ins + gr * D + c * 4, (gr < nrows) ? 16 : 0);
                }
                if (tid < 32) {
                    long long r0 = row0n + tid * 4;
                    long long rem = (long long)nrows - r0;
                    int sz = rem >= 4 ? 16 : (rem > 0 ? (int)rem * 4 : 0);
                    cp16(sbase + (buf ? PSEG0 : PSEG1) + (uint32_t)tid * 16u,
                         batch + r0, sz);
                }
            }
            cp_commit();
        }

        float acc[2][4][4];
#pragma unroll
        for (int m = 0; m < 2; m++)
#pragma unroll
            for (int i = 0; i < 4; i++)
#pragma unroll
                for (int j = 0; j < 4; j++) acc[m][i][j] = 0.f;
        gemm_pass3_32(aHi0, aLo0, bHi0, bLo0, acc);
        __syncthreads();   // A buffers free

        // h = relu(acc + b) into sH (reuses A region)
        float* sH = (float*)(smem + SA_HI);
        const float* sB = (const float*)(smem + PBIAS);
        {
            const int grp = lane >> 2, qp = lane & 3;
#pragma unroll
            for (int m = 0; m < 2; m++) {
                const int rA = wm * 32 + m * 16 + grp;
#pragma unroll
                for (int nt = 0; nt < 4; nt++) {
                    int c = wn * 32 + nt * 8 + qp * 2;
                    float b0 = sB[c], b1 = sB[c + 1];
                    *(float2*)(sH + rA * 128 + c) =
                        make_float2(fmaxf(acc[m][nt][0] + b0, 0.f),
                                    fmaxf(acc[m][nt][1] + b1, 0.f));
                    *(float2*)(sH + (rA + 8) * 128 + c) =
                        make_float2(fmaxf(acc[m][nt][2] + b0, 0.f),
                                    fmaxf(acc[m][nt][3] + b1, 0.f));
                }
            }
        }
        __syncthreads();

        // segment reduce: 4 groups of 32 rows, h preloaded to registers
        const int* sSeg = (const int*)(smem + (buf ? PSEG1 : PSEG0));
        const int row0 = t * 128;
        const int col = tid & (D - 1);
        const int rbeg = (tid >> 7) * 32;
        float hv[32];
#pragma unroll
        for (int r = 0; r < 32; r++) hv[r] = sH[(rbeg + r) * 128 + col];
        int cur = (row0 + rbeg < nrows) ? sSeg[rbeg] : -1;
        float run = 0.f, cnt = 0.f;
#pragma unroll
        for (int r = 0; r < 32; r++) {
            int s = (row0 + rbeg + r < nrows) ? sSeg[rbeg + r] : -1;
            if (s != cur) {
                if (cur >= 0) {
                    atomicAdd(&g_segsum[(size_t)cur * D + col], run);
                    if (col == 0) atomicAdd(&g_cnt[cur], cnt);
                }
                cur = s; run = 0.f; cnt = 0.f;
            }
            run += hv[r];
            cnt += 1.f;
        }
        if (cur >= 0) {
            atomicAdd(&g_segsum[(size_t)cur * D + col], run);
            if (col == 0) atomicAdd(&g_cnt[cur], cnt);
        }
        __syncthreads();   // sH reads done before next convert overwrites
        buf ^= 1;
    }
}

// ---------------------------------------------------------------------------
// fused small path (1024 threads, 128-row tiles — R7 shape, pipelined loop)
// ---------------------------------------------------------------------------
__global__ __launch_bounds__(1024, 1) void rho_fused_kernel(
    const __nv_bfloat16* __restrict__ W2hi, const __nv_bfloat16* __restrict__ W2lo,
    const __nv_bfloat16* __restrict__ R1hi, const __nv_bfloat16* __restrict__ R1lo,
    const __nv_bfloat16* __restrict__ R2hi, const __nv_bfloat16* __restrict__ R2lo,
    const float* __restrict__ b2, const float* __restrict__ rb1,
    const float* __restrict__ rb2, float* __restrict__ outp, int nrows)
{
    extern __shared__ __align__(16) char smem[];
    const uint32_t sbase = smem_u32(smem);
    const int tid = threadIdx.x;
    const int wid = tid >> 5, lane = tid & 31;
    const int wm = wid & 7, wn = wid >> 3;   // 8 M strips x 4 N strips (16x32)
    const int row0 = blockIdx.x * 128;

    float* sB = (float*)(smem + RBIAS);
    float* sCnt = (float*)(smem + RCNT);
    if (tid < D) {
        sB[tid] = b2[tid];
        sB[128 + tid] = rb1[tid];
        sB[256 + tid] = rb2[tid];
    }
    if (tid < 128) {
        int gr = row0 + tid;
        sCnt[tid] = (gr < nrows) ? g_cnt[gr] : 0.f;
    }
    load_W_pair<1024>(smem, W2hi, W2lo, tid);
    __syncthreads();

    // A tile: mean = segsum / max(cnt,1), split hi/lo
    for (int idx = tid; idx < 128 * 32; idx += 1024) {
        int r = idx >> 5, c4 = idx & 31;
        float4 v = make_float4(0.f, 0.f, 0.f, 0.f);
        int gr = row0 + r;
        if (gr < nrows) {
            v = *(const float4*)(g_segsum + (size_t)gr * D + c4 * 4);
            float s = 1.f / fmaxf(sCnt[r], 1.f);
            v.x *= s; v.y *= s; v.z *= s; v.w *= s;
        }
        float hx = __bfloat162float(__float2bfloat16_rn(v.x));
        float hy = __bfloat162float(__float2bfloat16_rn(v.y));
        float hz = __bfloat162float(__float2bfloat16_rn(v.z));
        float hw = __bfloat162float(__float2bfloat16_rn(v.w));
        uint32_t off = (uint32_t)r * SROW + (uint32_t)c4 * 8;
        *(uint2*)(smem + SA_HI + off) = make_uint2(pack_bf2(hx, hy), pack_bf2(hz, hw));
        *(uint2*)(smem + SA_LO + off) =
            make_uint2(pack_bf2(v.x - hx, v.y - hy), pack_bf2(v.z - hz, v.w - hw));
    }
    __syncthreads();

    const uint32_t aRow = (uint32_t)(wm * 16 + (lane & 15));
    const uint32_t aColB = (uint32_t)((lane >> 4) * 16);
    const uint32_t aHi0 = sbase + SA_HI + aRow * SROW + aColB;
    const uint32_t aLo0 = sbase + SA_LO + aRow * SROW + aColB;
    const uint32_t bRow = (uint32_t)((lane & 7) + ((lane & 16) ? 8 : 0));
    const uint32_t bColB = (uint32_t)(((lane & 8) ? 8 : 0) * 2);
    const uint32_t bHi0 = sbase + SW_HI + (bRow + (uint32_t)wn * 32u) * SROW + bColB;
    const uint32_t bLo0 = sbase + SW_LO + (bRow + (uint32_t)wn * 32u) * SROW + bColB;

    float acc[4][4];
    // ---- stage 1: u = mean@phiW2 + b2 (zero empty rows) ----
#pragma unroll
    for (int i = 0; i < 4; i++)
#pragma unroll
        for (int j = 0; j < 4; j++) acc[i][j] = 0.f;
    gemm_pass3_16(aHi0, aLo0, bHi0, bLo0, acc);
    __syncthreads();
    frag_store_A((char*)smem, acc, sB, sCnt, false, true, wm, wn, lane);
    load_W_pair<1024>((char*)smem, R1hi, R1lo, tid);
    __syncthreads();

    // ---- stage 2: v = relu(u@rhoW1 + rb1) ----
#pragma unroll
    for (int i = 0; i < 4; i++)
#pragma unroll
        for (int j = 0; j < 4; j++) acc[i][j] = 0.f;
    gemm_pass3_16(aHi0, aLo0, bHi0, bLo0, acc);
    __syncthreads();
    frag_store_A((char*)smem, acc, sB + 128, sCnt, true, false, wm, wn, lane);
    load_W_pair<1024>((char*)smem, R2hi, R2lo, tid);
    __syncthreads();

    // ---- stage 3: out = v@rhoW2 + rb2 ----
#pragma unroll
    for (int i = 0; i < 4; i++)
#pragma unroll
        for (int j = 0; j < 4; j++) acc[i][j] = 0.f;
    gemm_pass3_16(aHi0, aLo0, bHi0, bLo0, acc);
    {
        const int grp = lane >> 2, qp = lane & 3;
        const int rA = wm * 16 + grp;
        int gr0 = row0 + rA, gr1 = row0 + rA + 8;
#pragma unroll
        for (int nt = 0; nt < 4; nt++) {
            int c = wn * 32 + nt * 8 + qp * 2;
            float b0 = sB[256 + c], b1 = sB[256 + c + 1];
            if (gr0 < nrows)
                *(float2*)(outp + (size_t)gr0 * D + c) =
                    make_float2(acc[nt][0] + b0, acc[nt][1] + b1);
            if (gr1 < nrows)
                *(float2*)(outp + (size_t)gr1 * D + c) =
                    make_float2(acc[nt][2] + b0, acc[nt][3] + b1);
        }
    }
}

// ---------------------------------------------------------------------------
extern "C" void kernel_launch(void* const* d_in, const int* in_sizes, int n_in,
                              void* d_out, int out_size)
{
    const float* ins    = (const float*)d_in[0];
    const int*   batch  = (const int*)d_in[1];
    const float* phi_W1 = (const float*)d_in[3];
    const float* phi_b1 = (const float*)d_in[4];
    const float* phi_W2 = (const float*)d_in[5];
    const float* phi_b2 = (const float*)d_in[6];
    const float* rho_W1 = (const float*)d_in[7];
    const float* rho_b1 = (const float*)d_in[8];
    const float* rho_W2 = (const float*)d_in[9];
    const float* rho_b2 = (const float*)d_in[10];
    float* out = (float*)d_out;

    const int N = in_sizes[0] / D;
    const int ntiles = (N + 127) / 128;

    cudaFuncSetAttribute(phi_seg_kernel, cudaFuncAttributeMaxDynamicSharedMemorySize, PHI_SMEM);
    cudaFuncSetAttribute(rho_fused_kernel, cudaFuncAttributeMaxDynamicSharedMemorySize, RHO_SMEM);

    void *p_whi = nullptr, *p_wlo = nullptr;
    cudaGetSymbolAddress(&p_whi, g_Whi);
    cudaGetSymbolAddress(&p_wlo, g_Wlo);
    const __nv_bfloat16* Whi = (const __nv_bfloat16*)p_whi;
    const __nv_bfloat16* Wlo = (const __nv_bfloat16*)p_wlo;

    int zgrid = (NSEG * D / 4 + 255) / 256;
    zero_kernel<<<zgrid, 256>>>();
    prep_kernel<<<(4 * D * D + 255) / 256, 256>>>(phi_W1, phi_W2, rho_W1, rho_W2);

    int gphi = 148;
    if (gphi > ntiles) gphi = ntiles;
    phi_seg_kernel<<<gphi, 512, PHI_SMEM>>>(ins, batch,
        Whi + 0 * D * D, Wlo + 0 * D * D, phi_b1, N, ntiles);

    int g2 = (NSEG + 127) / 128;
    rho_fused_kernel<<<g2, 1024, RHO_SMEM>>>(
        Whi + 1 * D * D, Wlo + 1 * D * D,
        Whi + 2 * D * D, Wlo + 2 * D * D,
        Whi + 3 * D * D, Wlo + 3 * D * D,
        phi_b2, rho_b1, rho_b2, out, NSEG);
}

// round 10
// speedup vs baseline: 1.2421x; 1.2143x over previous
#include <cuda_runtime.h>
#include <cuda_bf16.h>
#include <cuda_fp16.h>
#include <cstdint>

#define D 128
#define NSEG 50000

// ---------------- device scratch ----------------
__device__ __align__(16) float g_segsum[NSEG * D];
__device__ __align__(16) float g_cnt[NSEG];
// rho weights: transposed bf16 hi/lo (slots 1..3 used)
__device__ __align__(16) __nv_bfloat16 g_Whi[4][D * D];
__device__ __align__(16) __nv_bfloat16 g_Wlo[4][D * D];
// phi W1: transposed fp16 hi/lo
__device__ __align__(16) __half g_WhiH[D * D];
__device__ __align__(16) __half g_WloH[D * D];

// ---------------- smem layouts (bytes) ----------------
#define SROW 272u
// phi (fp16 2-term): Whi, Wlo, A(single fp16), stage, meta
#define SW_HI 0u
#define SW_LO 34816u
#define SA    69632u
#define STAGE 104448u      // fp32 A staging, 65536 B
#define PBIAS 169984u
#define PSEG0 170496u
#define PSEG1 171008u
#define PHI_SMEM 171520u
// rho (bf16 3-term, R9 shape)
#define R_AHI 69632u
#define R_ALO 104448u
#define RBIAS 139264u
#define RCNT  140800u
#define RHO_SMEM 141312u

__device__ __forceinline__ uint32_t smem_u32(const void* p) {
    return (uint32_t)__cvta_generic_to_shared(p);
}

#define LDSM_X4(r, addr)                                                      \
    asm volatile("ldmatrix.sync.aligned.m8n8.x4.shared.b16 {%0,%1,%2,%3}, [%4];" \
                 : "=r"((r)[0]), "=r"((r)[1]), "=r"((r)[2]), "=r"((r)[3])     \
                 : "r"(addr))

#define MMA_BF16(d, a, b0, b1)                                                \
    asm volatile("mma.sync.aligned.m16n8k16.row.col.f32.bf16.bf16.f32 "       \
                 "{%0,%1,%2,%3},{%4,%5,%6,%7},{%8,%9},{%0,%1,%2,%3};"         \
                 : "+f"((d)[0]), "+f"((d)[1]), "+f"((d)[2]), "+f"((d)[3])     \
                 : "r"((a)[0]), "r"((a)[1]), "r"((a)[2]), "r"((a)[3]),        \
                   "r"(b0), "r"(b1))

#define MMA_F16(d, a, b0, b1)                                                 \
    asm volatile("mma.sync.aligned.m16n8k16.row.col.f32.f16.f16.f32 "         \
                 "{%0,%1,%2,%3},{%4,%5,%6,%7},{%8,%9},{%0,%1,%2,%3};"         \
                 : "+f"((d)[0]), "+f"((d)[1]), "+f"((d)[2]), "+f"((d)[3])     \
                 : "r"((a)[0]), "r"((a)[1]), "r"((a)[2]), "r"((a)[3]),        \
                   "r"(b0), "r"(b1))

__device__ __forceinline__ uint32_t pack_bf2(float x, float y) {
    __nv_bfloat162 t = __floats2bfloat162_rn(x, y);
    return *(uint32_t*)&t;
}
__device__ __forceinline__ uint32_t pack_h2(float x, float y) {
    __half2 t = __floats2half2_rn(x, y);
    return *(uint32_t*)&t;
}
__device__ __forceinline__ void cp16(uint32_t dst, const void* src, int bytes) {
    asm volatile("cp.async.cg.shared.global [%0], [%1], 16, %2;"
                 :: "r"(dst), "l"(src), "r"(bytes) : "memory");
}
__device__ __forceinline__ void cp_commit() {
    asm volatile("cp.async.commit_group;" ::: "memory");
}
__device__ __forceinline__ void cp_wait0() {
    asm volatile("cp.async.wait_group 0;" ::: "memory");
}

// ---------------------------------------------------------------------------
__global__ void prep_kernel(const float* __restrict__ W0, const float* __restrict__ W1,
                            const float* __restrict__ W2, const float* __restrict__ W3) {
    int i = blockIdx.x * blockDim.x + threadIdx.x;
    if (i >= 4 * D * D) return;
    const float* Ws[4] = {W0, W1, W2, W3};
    int mat = i >> 14;
    int e = i & (D * D - 1);
    int n = e >> 7, k = e & (D - 1);
    float w = Ws[mat][k * D + n];
    if (mat == 0) {
        __half hi = __float2half_rn(w);
        float lo = w - __half2float(hi);
        g_WhiH[n * D + k] = hi;
        g_WloH[n * D + k] = __float2half_rn(lo);
    } else {
        __nv_bfloat16 hi = __float2bfloat16_rn(w);
        float lo = w - __bfloat162float(hi);
        g_Whi[mat][n * D + k] = hi;
        g_Wlo[mat][n * D + k] = __float2bfloat16_rn(lo);
    }
}

__global__ void zero_kernel() {
    int i = blockIdx.x * blockDim.x + threadIdx.x;
    float4 z = make_float4(0.f, 0.f, 0.f, 0.f);
    if (i < NSEG * D / 4) ((float4*)g_segsum)[i] = z;
    if (i < NSEG / 4) ((float4*)g_cnt)[i] = z;
}

// ---------------------------------------------------------------------------
template <int NTHR, typename T>
__device__ __forceinline__ void load_W_pair(char* smem,
                                            const T* __restrict__ Whi,
                                            const T* __restrict__ Wlo,
                                            int tid) {
    for (int idx = tid; idx < 128 * 16; idx += NTHR) {
        int r = idx >> 4, ch = idx & 15;
        uint32_t off = (uint32_t)r * SROW + (uint32_t)ch * 16;
        *(uint4*)(smem + SW_HI + off) = *(const uint4*)(Whi + r * D + ch * 8);
        *(uint4*)(smem + SW_LO + off) = *(const uint4*)(Wlo + r * D + ch * 8);
    }
}

// ======== phi: fp16 2-term, 32x32 warp tile, pipelined ========
// acc[2][4][4]; per k: 6 LDSM, 16 MMA.
__device__ __forceinline__ void gemm_pass2_32(uint32_t aBase,
                                              uint32_t bHi, uint32_t bLo,
                                              float (*acc)[4][4]) {
    uint32_t A0[4], A1[4], WH0[4], WH1[4], WL0[4], WL1[4];
    LDSM_X4(A0, aBase);
    LDSM_X4(A1, aBase + 16u * SROW);
    LDSM_X4(WH0, bHi);
    LDSM_X4(WH1, bHi + 16u * SROW);
    LDSM_X4(WL0, bLo);
    LDSM_X4(WL1, bLo + 16u * SROW);
#pragma unroll
    for (int k = 0; k < 8; k++) {
        uint32_t A0n[4], A1n[4], WH0n[4], WH1n[4], WL0n[4], WL1n[4];
        if (k < 7) {
            LDSM_X4(A0n, aBase + 32);
            LDSM_X4(A1n, aBase + 16u * SROW + 32);
            LDSM_X4(WH0n, bHi + 32);
        }
        MMA_F16(acc[0][0], A0, WH0[0], WH0[1]);
        MMA_F16(acc[0][1], A0, WH0[2], WH0[3]);
        MMA_F16(acc[0][2], A0, WH1[0], WH1[1]);
        MMA_F16(acc[0][3], A0, WH1[2], WH1[3]);
        MMA_F16(acc[1][0], A1, WH0[0], WH0[1]);
        MMA_F16(acc[1][1], A1, WH0[2], WH0[3]);
        MMA_F16(acc[1][2], A1, WH1[0], WH1[1]);
        MMA_F16(acc[1][3], A1, WH1[2], WH1[3]);
        if (k < 7) {
            LDSM_X4(WH1n, bHi + 16u * SROW + 32);
            LDSM_X4(WL0n, bLo + 32);
            LDSM_X4(WL1n, bLo + 16u * SROW + 32);
        }
        MMA_F16(acc[0][0], A0, WL0[0], WL0[1]);
        MMA_F16(acc[0][1], A0, WL0[2], WL0[3]);
        MMA_F16(acc[0][2], A0, WL1[0], WL1[1]);
        MMA_F16(acc[0][3], A0, WL1[2], WL1[3]);
        MMA_F16(acc[1][0], A1, WL0[0], WL0[1]);
        MMA_F16(acc[1][1], A1, WL0[2], WL0[3]);
        MMA_F16(acc[1][2], A1, WL1[0], WL1[1]);
        MMA_F16(acc[1][3], A1, WL1[2], WL1[3]);
        if (k < 7) {
#pragma unroll
            for (int i = 0; i < 4; i++) {
                A0[i] = A0n[i]; A1[i] = A1n[i];
                WH0[i] = WH0n[i]; WH1[i] = WH1n[i];
                WL0[i] = WL0n[i]; WL1[i] = WL1n[i];
            }
            aBase += 32; bHi += 32; bLo += 32;
        }
    }
}

// ======== rho: bf16 3-term, 16x32 warp tile, pipelined (R9) ========
__device__ __forceinline__ void gemm_pass3_16(uint32_t aHi, uint32_t aLo,
                                              uint32_t bHi, uint32_t bLo,
                                              float (*acc)[4]) {
    uint32_t A0[4], A1[4], W0[4], V0[4];
    LDSM_X4(A0, aHi);
    LDSM_X4(A1, aLo);
    LDSM_X4(W0, bHi);
    LDSM_X4(V0, bLo);
#pragma unroll
    for (int k = 0; k < 8; k++) {
        uint32_t W1[4], V1[4];
        LDSM_X4(W1, bHi + 16u * SROW);
        LDSM_X4(V1, bLo + 16u * SROW);
        MMA_BF16(acc[0], A0, W0[0], W0[1]);
        MMA_BF16(acc[1], A0, W0[2], W0[3]);
        MMA_BF16(acc[0], A1, W0[0], W0[1]);
        MMA_BF16(acc[1], A1, W0[2], W0[3]);
        MMA_BF16(acc[0], A0, V0[0], V0[1]);
        MMA_BF16(acc[1], A0, V0[2], V0[3]);
        uint32_t A0n[4], A1n[4], W0n[4], V0n[4];
        if (k < 7) {
            LDSM_X4(A0n, aHi + 32);
            LDSM_X4(A1n, aLo + 32);
            LDSM_X4(W0n, bHi + 32);
            LDSM_X4(V0n, bLo + 32);
        }
        MMA_BF16(acc[2], A0, W1[0], W1[1]);
        MMA_BF16(acc[3], A0, W1[2], W1[3]);
        MMA_BF16(acc[2], A1, W1[0], W1[1]);
        MMA_BF16(acc[3], A1, W1[2], W1[3]);
        MMA_BF16(acc[2], A0, V1[0], V1[1]);
        MMA_BF16(acc[3], A0, V1[2], V1[3]);
        if (k < 7) {
#pragma unroll
            for (int i = 0; i < 4; i++) {
                A0[i] = A0n[i]; A1[i] = A1n[i];
                W0[i] = W0n[i]; V0[i] = V0n[i];
            }
            aHi += 32; aLo += 32; bHi += 32; bLo += 32;
        }
    }
}

// rho fragments (+bias, opt relu, opt zero-empty) back to A smem as bf16 hi/lo
__device__ __forceinline__ void frag_store_A(char* smem, float (*acc)[4],
                                             const float* bias, const float* sCnt,
                                             bool relu, bool zeroE,
                                             int wm, int wn, int lane) {
    const int grp = lane >> 2, qp = lane & 3;
    const int rA = wm * 16 + grp;
    bool z0 = zeroE && (sCnt[rA] <= 0.f);
    bool z1 = zeroE && (sCnt[rA + 8] <= 0.f);
#pragma unroll
    for (int nt = 0; nt < 4; nt++) {
        int c = wn * 32 + nt * 8 + qp * 2;
        float b0 = bias[c], b1 = bias[c + 1];
        float x0 = acc[nt][0] + b0, y0 = acc[nt][1] + b1;
        float x1 = acc[nt][2] + b0, y1 = acc[nt][3] + b1;
        if (relu) {
            x0 = fmaxf(x0, 0.f); y0 = fmaxf(y0, 0.f);
            x1 = fmaxf(x1, 0.f); y1 = fmaxf(y1, 0.f);
        }
        if (z0) { x0 = 0.f; y0 = 0.f; }
        if (z1) { x1 = 0.f; y1 = 0.f; }
        float hx0 = __bfloat162float(__float2bfloat16_rn(x0));
        float hy0 = __bfloat162float(__float2bfloat16_rn(y0));
        float hx1 = __bfloat162float(__float2bfloat16_rn(x1));
        float hy1 = __bfloat162float(__float2bfloat16_rn(y1));
        uint32_t o0 = (uint32_t)rA * SROW + (uint32_t)c * 2;
        uint32_t o1 = (uint32_t)(rA + 8) * SROW + (uint32_t)c * 2;
        *(uint32_t*)(smem + R_AHI + o0) = pack_bf2(hx0, hy0);
        *(uint32_t*)(smem + R_ALO + o0) = pack_bf2(x0 - hx0, y0 - hy0);
        *(uint32_t*)(smem + R_AHI + o1) = pack_bf2(hx1, hy1);
        *(uint32_t*)(smem + R_ALO + o1) = pack_bf2(x1 - hx1, y1 - hy1);
    }
}

// ---------------------------------------------------------------------------
// PERSISTENT phi kernel: 512 threads, 4x4 grid of 32x32 tiles, fp16 2-term.
// ---------------------------------------------------------------------------
__global__ __launch_bounds__(512, 1) void phi_seg_kernel(
    const float* __restrict__ ins, const int* __restrict__ batch,
    const __half* __restrict__ Whi, const __half* __restrict__ Wlo,
    const float* __restrict__ bias, int nrows, int ntiles)
{
    extern __shared__ __align__(16) char smem[];
    const uint32_t sbase = smem_u32(smem);
    const int tid = threadIdx.x;
    const int wid = tid >> 5, lane = tid & 31;
    const int wm = wid & 3, wn = wid >> 2;

    // prologue prefetch of first tile
    {
        int t = blockIdx.x;
        if (t < ntiles) {
            long long row0 = (long long)t * 128;
            for (int idx = tid; idx < 4096; idx += 512) {
                int r = idx >> 5, c = idx & 31;
                long long gr = row0 + r;
                cp16(sbase + STAGE + (uint32_t)idx * 16u,
                     ins + gr * D + c * 4, (gr < nrows) ? 16 : 0);
            }
            if (tid < 32) {
                long long r0 = row0 + tid * 4;
                long long rem = (long long)nrows - r0;
                int sz = rem >= 4 ? 16 : (rem > 0 ? (int)rem * 4 : 0);
                cp16(sbase + PSEG0 + (uint32_t)tid * 16u, batch + r0, sz);
            }
        }
        cp_commit();
    }
    load_W_pair<512, __half>(smem, Whi, Wlo, tid);
    if (tid < D) ((float*)(smem + PBIAS))[tid] = bias[tid];

    // lane-resolved operand base addresses (32x32 tiles)
    const uint32_t aRow = (uint32_t)(wm * 32 + (lane & 15));
    const uint32_t aColB = (uint32_t)((lane >> 4) * 16);
    const uint32_t aBase0 = sbase + SA + aRow * SROW + aColB;
    const uint32_t bRow = (uint32_t)((lane & 7) + ((lane & 16) ? 8 : 0));
    const uint32_t bColB = (uint32_t)(((lane & 8) ? 8 : 0) * 2);
    const uint32_t bHi0 = sbase + SW_HI + (bRow + (uint32_t)wn * 32u) * SROW + bColB;
    const uint32_t bLo0 = sbase + SW_LO + (bRow + (uint32_t)wn * 32u) * SROW + bColB;

    int buf = 0;
    for (int t = blockIdx.x; t < ntiles; t += gridDim.x) {
        cp_wait0();
        __syncthreads();
        // convert staged fp32 -> fp16 (single buffer)
        for (int idx = tid; idx < 4096; idx += 512) {
            int r = idx >> 5, c4 = idx & 31;
            float4 v = *(const float4*)(smem + STAGE + (uint32_t)r * 512u + (uint32_t)c4 * 16u);
            uint32_t off = (uint32_t)r * SROW + (uint32_t)c4 * 8;
            *(uint2*)(smem + SA + off) = make_uint2(pack_h2(v.x, v.y), pack_h2(v.z, v.w));
        }
        __syncthreads();   // stage free -> prefetch next tile
        {
            int nt_ = t + gridDim.x;
            if (nt_ < ntiles) {
                long long row0n = (long long)nt_ * 128;
                for (int idx = tid; idx < 4096; idx += 512) {
                    int r = idx >> 5, c = idx & 31;
                    long long gr = row0n + r;
                    cp16(sbase + STAGE + (uint32_t)idx * 16u,
                         ins + gr * D + c * 4, (gr < nrows) ? 16 : 0);
                }
                if (tid < 32) {
                    long long r0 = row0n + tid * 4;
                    long long rem = (long long)nrows - r0;
                    int sz = rem >= 4 ? 16 : (rem > 0 ? (int)rem * 4 : 0);
                    cp16(sbase + (buf ? PSEG0 : PSEG1) + (uint32_t)tid * 16u,
                         batch + r0, sz);
                }
            }
            cp_commit();
        }

        float acc[2][4][4];
#pragma unroll
        for (int m = 0; m < 2; m++)
#pragma unroll
            for (int i = 0; i < 4; i++)
#pragma unroll
                for (int j = 0; j < 4; j++) acc[m][i][j] = 0.f;
        gemm_pass2_32(aBase0, bHi0, bLo0, acc);
        __syncthreads();   // A buffer reads done

        // h = relu(acc + b) stored fp16 into SA
        const float* sB = (const float*)(smem + PBIAS);
        {
            const int grp = lane >> 2, qp = lane & 3;
#pragma unroll
            for (int m = 0; m < 2; m++) {
                const int rA = wm * 32 + m * 16 + grp;
#pragma unroll
                for (int nt = 0; nt < 4; nt++) {
                    int c = wn * 32 + nt * 8 + qp * 2;
                    float b0 = sB[c], b1 = sB[c + 1];
                    *(uint32_t*)(smem + SA + (uint32_t)rA * SROW + (uint32_t)c * 2) =
                        pack_h2(fmaxf(acc[m][nt][0] + b0, 0.f),
                                fmaxf(acc[m][nt][1] + b1, 0.f));
                    *(uint32_t*)(smem + SA + (uint32_t)(rA + 8) * SROW + (uint32_t)c * 2) =
                        pack_h2(fmaxf(acc[m][nt][2] + b0, 0.f),
                                fmaxf(acc[m][nt][3] + b1, 0.f));
                }
            }
        }
        __syncthreads();

        // segment reduce: 4 groups of 32 rows, h preloaded to registers
        const int* sSeg = (const int*)(smem + (buf ? PSEG1 : PSEG0));
        const int row0 = t * 128;
        const int col = tid & (D - 1);
        const int rbeg = (tid >> 7) * 32;
        float hv[32];
#pragma unroll
        for (int r = 0; r < 32; r++)
            hv[r] = __half2float(*(const __half*)(
                smem + SA + (uint32_t)(rbeg + r) * SROW + (uint32_t)col * 2));
        int cur = (row0 + rbeg < nrows) ? sSeg[rbeg] : -1;
        float run = 0.f, cnt = 0.f;
#pragma unroll
        for (int r = 0; r < 32; r++) {
            int s = (row0 + rbeg + r < nrows) ? sSeg[rbeg + r] : -1;
            if (s != cur) {
                if (cur >= 0) {
                    atomicAdd(&g_segsum[(size_t)cur * D + col], run);
                    if (col == 0) atomicAdd(&g_cnt[cur], cnt);
                }
                cur = s; run = 0.f; cnt = 0.f;
            }
            run += hv[r];
            cnt += 1.f;
        }
        if (cur >= 0) {
            atomicAdd(&g_segsum[(size_t)cur * D + col], run);
            if (col == 0) atomicAdd(&g_cnt[cur], cnt);
        }
        __syncthreads();   // SA reads done before next convert overwrites
        buf ^= 1;
    }
}

// ---------------------------------------------------------------------------
// fused small path (1024 threads, 128-row tiles, bf16 3-term — R9)
// ---------------------------------------------------------------------------
__global__ __launch_bounds__(1024, 1) void rho_fused_kernel(
    const __nv_bfloat16* __restrict__ W2hi, const __nv_bfloat16* __restrict__ W2lo,
    const __nv_bfloat16* __restrict__ R1hi, const __nv_bfloat16* __restrict__ R1lo,
    const __nv_bfloat16* __restrict__ R2hi, const __nv_bfloat16* __restrict__ R2lo,
    const float* __restrict__ b2, const float* __restrict__ rb1,
    const float* __restrict__ rb2, float* __restrict__ outp, int nrows)
{
    extern __shared__ __align__(16) char smem[];
    const uint32_t sbase = smem_u32(smem);
    const int tid = threadIdx.x;
    const int wid = tid >> 5, lane = tid & 31;
    const int wm = wid & 7, wn = wid >> 3;
    const int row0 = blockIdx.x * 128;

    float* sB = (float*)(smem + RBIAS);
    float* sCnt = (float*)(smem + RCNT);
    if (tid < D) {
        sB[tid] = b2[tid];
        sB[128 + tid] = rb1[tid];
        sB[256 + tid] = rb2[tid];
    }
    if (tid < 128) {
        int gr = row0 + tid;
        sCnt[tid] = (gr < nrows) ? g_cnt[gr] : 0.f;
    }
    load_W_pair<1024, __nv_bfloat16>(smem, W2hi, W2lo, tid);
    __syncthreads();

    // A tile: mean = segsum / max(cnt,1), split hi/lo
    for (int idx = tid; idx < 128 * 32; idx += 1024) {
        int r = idx >> 5, c4 = idx & 31;
        float4 v = make_float4(0.f, 0.f, 0.f, 0.f);
        int gr = row0 + r;
        if (gr < nrows) {
            v = *(const float4*)(g_segsum + (size_t)gr * D + c4 * 4);
            float s = 1.f / fmaxf(sCnt[r], 1.f);
            v.x *= s; v.y *= s; v.z *= s; v.w *= s;
        }
        float hx = __bfloat162float(__float2bfloat16_rn(v.x));
        float hy = __bfloat162float(__float2bfloat16_rn(v.y));
        float hz = __bfloat162float(__float2bfloat16_rn(v.z));
        float hw = __bfloat162float(__float2bfloat16_rn(v.w));
        uint32_t off = (uint32_t)r * SROW + (uint32_t)c4 * 8;
        *(uint2*)(smem + R_AHI + off) = make_uint2(pack_bf2(hx, hy), pack_bf2(hz, hw));
        *(uint2*)(smem + R_ALO + off) =
            make_uint2(pack_bf2(v.x - hx, v.y - hy), pack_bf2(v.z - hz, v.w - hw));
    }
    __syncthreads();

    const uint32_t aRow = (uint32_t)(wm * 16 + (lane & 15));
    const uint32_t aColB = (uint32_t)((lane >> 4) * 16);
    const uint32_t aHi0 = sbase + R_AHI + aRow * SROW + aColB;
    const uint32_t aLo0 = sbase + R_ALO + aRow * SROW + aColB;
    const uint32_t bRow = (uint32_t)((lane & 7) + ((lane & 16) ? 8 : 0));
    const uint32_t bColB = (uint32_t)(((lane & 8) ? 8 : 0) * 2);
    const uint32_t bHi0 = sbase + SW_HI + (bRow + (uint32_t)wn * 32u) * SROW + bColB;
    const uint32_t bLo0 = sbase + SW_LO + (bRow + (uint32_t)wn * 32u) * SROW + bColB;

    float acc[4][4];
    // ---- stage 1: u = mean@phiW2 + b2 (zero empty rows) ----
#pragma unroll
    for (int i = 0; i < 4; i++)
#pragma unroll
        for (int j = 0; j < 4; j++) acc[i][j] = 0.f;
    gemm_pass3_16(aHi0, aLo0, bHi0, bLo0, acc);
    __syncthreads();
    frag_store_A((char*)smem, acc, sB, sCnt, false, true, wm, wn, lane);
    load_W_pair<1024, __nv_bfloat16>((char*)smem, R1hi, R1lo, tid);
    __syncthreads();

    // ---- stage 2: v = relu(u@rhoW1 + rb1) ----
#pragma unroll
    for (int i = 0; i < 4; i++)
#pragma unroll
        for (int j = 0; j < 4; j++) acc[i][j] = 0.f;
    gemm_pass3_16(aHi0, aLo0, bHi0, bLo0, acc);
    __syncthreads();
    frag_store_A((char*)smem, acc, sB + 128, sCnt, true, false, wm, wn, lane);
    load_W_pair<1024, __nv_bfloat16>((char*)smem, R2hi, R2lo, tid);
    __syncthreads();

    // ---- stage 3: out = v@rhoW2 + rb2 ----
#pragma unroll
    for (int i = 0; i < 4; i++)
#pragma unroll
        for (int j = 0; j < 4; j++) acc[i][j] = 0.f;
    gemm_pass3_16(aHi0, aLo0, bHi0, bLo0, acc);
    {
        const int grp = lane >> 2, qp = lane & 3;
        const int rA = wm * 16 + grp;
        int gr0 = row0 + rA, gr1 = row0 + rA + 8;
#pragma unroll
        for (int nt = 0; nt < 4; nt++) {
            int c = wn * 32 + nt * 8 + qp * 2;
            float b0 = sB[256 + c], b1 = sB[256 + c + 1];
            if (gr0 < nrows)
                *(float2*)(outp + (size_t)gr0 * D + c) =
                    make_float2(acc[nt][0] + b0, acc[nt][1] + b1);
            if (gr1 < nrows)
                *(float2*)(outp + (size_t)gr1 * D + c) =
                    make_float2(acc[nt][2] + b0, acc[nt][3] + b1);
        }
    }
}

// ---------------------------------------------------------------------------
extern "C" void kernel_launch(void* const* d_in, const int* in_sizes, int n_in,
                              void* d_out, int out_size)
{
    const float* ins    = (const float*)d_in[0];
    const int*   batch  = (const int*)d_in[1];
    const float* phi_W1 = (const float*)d_in[3];
    const float* phi_b1 = (const float*)d_in[4];
    const float* phi_W2 = (const float*)d_in[5];
    const float* phi_b2 = (const float*)d_in[6];
    const float* rho_W1 = (const float*)d_in[7];
    const float* rho_b1 = (const float*)d_in[8];
    const float* rho_W2 = (const float*)d_in[9];
    const float* rho_b2 = (const float*)d_in[10];
    float* out = (float*)d_out;

    const int N = in_sizes[0] / D;
    const int ntiles = (N + 127) / 128;

    cudaFuncSetAttribute(phi_seg_kernel, cudaFuncAttributeMaxDynamicSharedMemorySize, PHI_SMEM);
    cudaFuncSetAttribute(rho_fused_kernel, cudaFuncAttributeMaxDynamicSharedMemorySize, RHO_SMEM);

    void *p_whi = nullptr, *p_wlo = nullptr, *p_whiH = nullptr, *p_wloH = nullptr;
    cudaGetSymbolAddress(&p_whi, g_Whi);
    cudaGetSymbolAddress(&p_wlo, g_Wlo);
    cudaGetSymbolAddress(&p_whiH, g_WhiH);
    cudaGetSymbolAddress(&p_wloH, g_WloH);
    const __nv_bfloat16* Whi = (const __nv_bfloat16*)p_whi;
    const __nv_bfloat16* Wlo = (const __nv_bfloat16*)p_wlo;

    int zgrid = (NSEG * D / 4 + 255) / 256;
    zero_kernel<<<zgrid, 256>>>();
    prep_kernel<<<(4 * D * D + 255) / 256, 256>>>(phi_W1, phi_W2, rho_W1, rho_W2);

    int gphi = 148;
    if (gphi > ntiles) gphi = ntiles;
    phi_seg_kernel<<<gphi, 512, PHI_SMEM>>>(ins, batch,
        (const __half*)p_whiH, (const __half*)p_wloH, phi_b1, N, ntiles);

    int g2 = (NSEG + 127) / 128;
    rho_fused_kernel<<<g2, 1024, RHO_SMEM>>>(
        Whi + 1 * D * D, Wlo + 1 * D * D,
        Whi + 2 * D * D, Wlo + 2 * D * D,
        Whi + 3 * D * D, Wlo + 3 * D * D,
        phi_b2, rho_b1, rho_b2, out, NSEG);
}

// round 11
// speedup vs baseline: 1.5738x; 1.2670x over previous
#include <cuda_runtime.h>
#include <cuda_fp16.h>
#include <cstdint>

#define D 128
#define NSEG 50000

// ---------------- device scratch ----------------
__device__ __align__(16) float g_segsum[NSEG * D];
__device__ __align__(16) float g_cnt[NSEG];
// transposed weights Wt[n][k] = W[k][n], fp16 hi/lo split, 4 matrices
__device__ __align__(16) __half g_Whi[4][D * D];
__device__ __align__(16) __half g_Wlo[4][D * D];

// ---------------- smem layouts (bytes) ----------------
#define SROW 272u
// shared W region (fp16 hi/lo)
#define SW_HI 0u
#define SW_LO 34816u
// phi: A(single fp16), stage, meta
#define SA    69632u
#define STAGE 104448u      // fp32 A staging, 65536 B
#define PBIAS 169984u
#define PSEG0 170496u
#define PSEG1 171008u
#define PHI_SMEM 171520u
// rho: A(single fp16), biases, counts
#define R_A   69632u
#define RBIAS 104448u      // 3 x 512 B
#define RCNT  105984u      // 512 B
#define RHO_SMEM 106496u

__device__ __forceinline__ uint32_t smem_u32(const void* p) {
    return (uint32_t)__cvta_generic_to_shared(p);
}

#define LDSM_X4(r, addr)                                                      \
    asm volatile("ldmatrix.sync.aligned.m8n8.x4.shared.b16 {%0,%1,%2,%3}, [%4];" \
                 : "=r"((r)[0]), "=r"((r)[1]), "=r"((r)[2]), "=r"((r)[3])     \
                 : "r"(addr))

#define MMA_F16(d, a, b0, b1)                                                 \
    asm volatile("mma.sync.aligned.m16n8k16.row.col.f32.f16.f16.f32 "         \
                 "{%0,%1,%2,%3},{%4,%5,%6,%7},{%8,%9},{%0,%1,%2,%3};"         \
                 : "+f"((d)[0]), "+f"((d)[1]), "+f"((d)[2]), "+f"((d)[3])     \
                 : "r"((a)[0]), "r"((a)[1]), "r"((a)[2]), "r"((a)[3]),        \
                   "r"(b0), "r"(b1))

__device__ __forceinline__ uint32_t pack_h2(float x, float y) {
    __half2 t = __floats2half2_rn(x, y);
    return *(uint32_t*)&t;
}
__device__ __forceinline__ void cp16(uint32_t dst, const void* src, int bytes) {
    asm volatile("cp.async.cg.shared.global [%0], [%1], 16, %2;"
                 :: "r"(dst), "l"(src), "r"(bytes) : "memory");
}
__device__ __forceinline__ void cp_commit() {
    asm volatile("cp.async.commit_group;" ::: "memory");
}
__device__ __forceinline__ void cp_wait0() {
    asm volatile("cp.async.wait_group 0;" ::: "memory");
}

// ---------------------------------------------------------------------------
__global__ void prep_kernel(const float* __restrict__ W0, const float* __restrict__ W1,
                            const float* __restrict__ W2, const float* __restrict__ W3) {
    int i = blockIdx.x * blockDim.x + threadIdx.x;
    if (i >= 4 * D * D) return;
    const float* Ws[4] = {W0, W1, W2, W3};
    int mat = i >> 14;
    int e = i & (D * D - 1);
    int n = e >> 7, k = e & (D - 1);
    float w = Ws[mat][k * D + n];
    __half hi = __float2half_rn(w);
    float lo = w - __half2float(hi);
    g_Whi[mat][n * D + k] = hi;
    g_Wlo[mat][n * D + k] = __float2half_rn(lo);
}

__global__ void zero_kernel() {
    int i = blockIdx.x * blockDim.x + threadIdx.x;
    float4 z = make_float4(0.f, 0.f, 0.f, 0.f);
    if (i < NSEG * D / 4) ((float4*)g_segsum)[i] = z;
    if (i < NSEG / 4) ((float4*)g_cnt)[i] = z;
}

// ---------------------------------------------------------------------------
template <int NTHR>
__device__ __forceinline__ void load_W_pair(char* smem,
                                            const __half* __restrict__ Whi,
                                            const __half* __restrict__ Wlo,
                                            int tid) {
    for (int idx = tid; idx < 128 * 16; idx += NTHR) {
        int r = idx >> 4, ch = idx & 15;
        uint32_t off = (uint32_t)r * SROW + (uint32_t)ch * 16;
        *(uint4*)(smem + SW_HI + off) = *(const uint4*)(Whi + r * D + ch * 8);
        *(uint4*)(smem + SW_LO + off) = *(const uint4*)(Wlo + r * D + ch * 8);
    }
}

// ======== phi: fp16 2-term, 32x32 warp tile, pipelined (16 warps) ========
__device__ __forceinline__ void gemm_pass2_32(uint32_t aBase,
                                              uint32_t bHi, uint32_t bLo,
                                              float (*acc)[4][4]) {
    uint32_t A0[4], A1[4], WH0[4], WH1[4], WL0[4], WL1[4];
    LDSM_X4(A0, aBase);
    LDSM_X4(A1, aBase + 16u * SROW);
    LDSM_X4(WH0, bHi);
    LDSM_X4(WH1, bHi + 16u * SROW);
    LDSM_X4(WL0, bLo);
    LDSM_X4(WL1, bLo + 16u * SROW);
#pragma unroll
    for (int k = 0; k < 8; k++) {
        uint32_t A0n[4], A1n[4], WH0n[4], WH1n[4], WL0n[4], WL1n[4];
        if (k < 7) {
            LDSM_X4(A0n, aBase + 32);
            LDSM_X4(A1n, aBase + 16u * SROW + 32);
            LDSM_X4(WH0n, bHi + 32);
        }
        MMA_F16(acc[0][0], A0, WH0[0], WH0[1]);
        MMA_F16(acc[0][1], A0, WH0[2], WH0[3]);
        MMA_F16(acc[0][2], A0, WH1[0], WH1[1]);
        MMA_F16(acc[0][3], A0, WH1[2], WH1[3]);
        MMA_F16(acc[1][0], A1, WH0[0], WH0[1]);
        MMA_F16(acc[1][1], A1, WH0[2], WH0[3]);
        MMA_F16(acc[1][2], A1, WH1[0], WH1[1]);
        MMA_F16(acc[1][3], A1, WH1[2], WH1[3]);
        if (k < 7) {
            LDSM_X4(WH1n, bHi + 16u * SROW + 32);
            LDSM_X4(WL0n, bLo + 32);
            LDSM_X4(WL1n, bLo + 16u * SROW + 32);
        }
        MMA_F16(acc[0][0], A0, WL0[0], WL0[1]);
        MMA_F16(acc[0][1], A0, WL0[2], WL0[3]);
        MMA_F16(acc[0][2], A0, WL1[0], WL1[1]);
        MMA_F16(acc[0][3], A0, WL1[2], WL1[3]);
        MMA_F16(acc[1][0], A1, WL0[0], WL0[1]);
        MMA_F16(acc[1][1], A1, WL0[2], WL0[3]);
        MMA_F16(acc[1][2], A1, WL1[0], WL1[1]);
        MMA_F16(acc[1][3], A1, WL1[2], WL1[3]);
        if (k < 7) {
#pragma unroll
            for (int i = 0; i < 4; i++) {
                A0[i] = A0n[i]; A1[i] = A1n[i];
                WH0[i] = WH0n[i]; WH1[i] = WH1n[i];
                WL0[i] = WL0n[i]; WL1[i] = WL1n[i];
            }
            aBase += 32; bHi += 32; bLo += 32;
        }
    }
}

// ======== rho: fp16 2-term, 16x32 warp tile, pipelined (32 warps) ========
__device__ __forceinline__ void gemm_pass2_16(uint32_t aBase,
                                              uint32_t bHi, uint32_t bLo,
                                              float (*acc)[4]) {
    uint32_t A0[4], WH0[4], WH1[4], WL0[4], WL1[4];
    LDSM_X4(A0, aBase);
    LDSM_X4(WH0, bHi);
    LDSM_X4(WH1, bHi + 16u * SROW);
    LDSM_X4(WL0, bLo);
    LDSM_X4(WL1, bLo + 16u * SROW);
#pragma unroll
    for (int k = 0; k < 8; k++) {
        uint32_t A0n[4], WH0n[4], WH1n[4], WL0n[4], WL1n[4];
        if (k < 7) {
            LDSM_X4(A0n, aBase + 32);
            LDSM_X4(WH0n, bHi + 32);
            LDSM_X4(WH1n, bHi + 16u * SROW + 32);
        }
        MMA_F16(acc[0], A0, WH0[0], WH0[1]);
        MMA_F16(acc[1], A0, WH0[2], WH0[3]);
        MMA_F16(acc[2], A0, WH1[0], WH1[1]);
        MMA_F16(acc[3], A0, WH1[2], WH1[3]);
        if (k < 7) {
            LDSM_X4(WL0n, bLo + 32);
            LDSM_X4(WL1n, bLo + 16u * SROW + 32);
        }
        MMA_F16(acc[0], A0, WL0[0], WL0[1]);
        MMA_F16(acc[1], A0, WL0[2], WL0[3]);
        MMA_F16(acc[2], A0, WL1[0], WL1[1]);
        MMA_F16(acc[3], A0, WL1[2], WL1[3]);
        if (k < 7) {
#pragma unroll
            for (int i = 0; i < 4; i++) {
                A0[i] = A0n[i];
                WH0[i] = WH0n[i]; WH1[i] = WH1n[i];
                WL0[i] = WL0n[i]; WL1[i] = WL1n[i];
            }
            aBase += 32; bHi += 32; bLo += 32;
        }
    }
}

// rho fragments (+bias, opt relu, opt zero-empty) back to A smem as single fp16
__device__ __forceinline__ void frag_store_A(char* smem, float (*acc)[4],
                                             const float* bias, const float* sCnt,
                                             bool relu, bool zeroE,
                                             int wm, int wn, int lane) {
    const int grp = lane >> 2, qp = lane & 3;
    const int rA = wm * 16 + grp;
    bool z0 = zeroE && (sCnt[rA] <= 0.f);
    bool z1 = zeroE && (sCnt[rA + 8] <= 0.f);
#pragma unroll
    for (int nt = 0; nt < 4; nt++) {
        int c = wn * 32 + nt * 8 + qp * 2;
        float b0 = bias[c], b1 = bias[c + 1];
        float x0 = acc[nt][0] + b0, y0 = acc[nt][1] + b1;
        float x1 = acc[nt][2] + b0, y1 = acc[nt][3] + b1;
        if (relu) {
            x0 = fmaxf(x0, 0.f); y0 = fmaxf(y0, 0.f);
            x1 = fmaxf(x1, 0.f); y1 = fmaxf(y1, 0.f);
        }
        if (z0) { x0 = 0.f; y0 = 0.f; }
        if (z1) { x1 = 0.f; y1 = 0.f; }
        uint32_t o0 = (uint32_t)rA * SROW + (uint32_t)c * 2;
        uint32_t o1 = (uint32_t)(rA + 8) * SROW + (uint32_t)c * 2;
        *(uint32_t*)(smem + R_A + o0) = pack_h2(x0, y0);
        *(uint32_t*)(smem + R_A + o1) = pack_h2(x1, y1);
    }
}

// ---------------------------------------------------------------------------
// PERSISTENT phi kernel: 512 threads, 4x4 grid of 32x32 tiles, fp16 2-term.
// Segment reduce uses float4 vector atomics.
// ---------------------------------------------------------------------------
__global__ __launch_bounds__(512, 1) void phi_seg_kernel(
    const float* __restrict__ ins, const int* __restrict__ batch,
    const __half* __restrict__ Whi, const __half* __restrict__ Wlo,
    const float* __restrict__ bias, int nrows, int ntiles)
{
    extern __shared__ __align__(16) char smem[];
    const uint32_t sbase = smem_u32(smem);
    const int tid = threadIdx.x;
    const int wid = tid >> 5, lane = tid & 31;
    const int wm = wid & 3, wn = wid >> 2;

    // prologue prefetch of first tile
    {
        int t = blockIdx.x;
        if (t < ntiles) {
            long long row0 = (long long)t * 128;
            for (int idx = tid; idx < 4096; idx += 512) {
                int r = idx >> 5, c = idx & 31;
                long long gr = row0 + r;
                cp16(sbase + STAGE + (uint32_t)idx * 16u,
                     ins + gr * D + c * 4, (gr < nrows) ? 16 : 0);
            }
            if (tid < 32) {
                long long r0 = row0 + tid * 4;
                long long rem = (long long)nrows - r0;
                int sz = rem >= 4 ? 16 : (rem > 0 ? (int)rem * 4 : 0);
                cp16(sbase + PSEG0 + (uint32_t)tid * 16u, batch + r0, sz);
            }
        }
        cp_commit();
    }
    load_W_pair<512>(smem, Whi, Wlo, tid);
    if (tid < D) ((float*)(smem + PBIAS))[tid] = bias[tid];

    const uint32_t aRow = (uint32_t)(wm * 32 + (lane & 15));
    const uint32_t aColB = (uint32_t)((lane >> 4) * 16);
    const uint32_t aBase0 = sbase + SA + aRow * SROW + aColB;
    const uint32_t bRow = (uint32_t)((lane & 7) + ((lane & 16) ? 8 : 0));
    const uint32_t bColB = (uint32_t)(((lane & 8) ? 8 : 0) * 2);
    const uint32_t bHi0 = sbase + SW_HI + (bRow + (uint32_t)wn * 32u) * SROW + bColB;
    const uint32_t bLo0 = sbase + SW_LO + (bRow + (uint32_t)wn * 32u) * SROW + bColB;

    int buf = 0;
    for (int t = blockIdx.x; t < ntiles; t += gridDim.x) {
        cp_wait0();
        __syncthreads();
        // convert staged fp32 -> fp16
        for (int idx = tid; idx < 4096; idx += 512) {
            int r = idx >> 5, c4 = idx & 31;
            float4 v = *(const float4*)(smem + STAGE + (uint32_t)r * 512u + (uint32_t)c4 * 16u);
            uint32_t off = (uint32_t)r * SROW + (uint32_t)c4 * 8;
            *(uint2*)(smem + SA + off) = make_uint2(pack_h2(v.x, v.y), pack_h2(v.z, v.w));
        }
        __syncthreads();   // stage free -> prefetch next tile
        {
            int nt_ = t + gridDim.x;
            if (nt_ < ntiles) {
                long long row0n = (long long)nt_ * 128;
                for (int idx = tid; idx < 4096; idx += 512) {
                    int r = idx >> 5, c = idx & 31;
                    long long gr = row0n + r;
                    cp16(sbase + STAGE + (uint32_t)idx * 16u,
                         ins + gr * D + c * 4, (gr < nrows) ? 16 : 0);
                }
                if (tid < 32) {
                    long long r0 = row0n + tid * 4;
                    long long rem = (long long)nrows - r0;
                    int sz = rem >= 4 ? 16 : (rem > 0 ? (int)rem * 4 : 0);
                    cp16(sbase + (buf ? PSEG0 : PSEG1) + (uint32_t)tid * 16u,
                         batch + r0, sz);
                }
            }
            cp_commit();
        }

        float acc[2][4][4];
#pragma unroll
        for (int m = 0; m < 2; m++)
#pragma unroll
            for (int i = 0; i < 4; i++)
#pragma unroll
                for (int j = 0; j < 4; j++) acc[m][i][j] = 0.f;
        gemm_pass2_32(aBase0, bHi0, bLo0, acc);
        __syncthreads();   // A buffer reads done

        // h = relu(acc + b) stored fp16 into SA
        const float* sB = (const float*)(smem + PBIAS);
        {
            const int grp = lane >> 2, qp = lane & 3;
#pragma unroll
            for (int m = 0; m < 2; m++) {
                const int rA = wm * 32 + m * 16 + grp;
#pragma unroll
                for (int nt = 0; nt < 4; nt++) {
                    int c = wn * 32 + nt * 8 + qp * 2;
                    float b0 = sB[c], b1 = sB[c + 1];
                    *(uint32_t*)(smem + SA + (uint32_t)rA * SROW + (uint32_t)c * 2) =
                        pack_h2(fmaxf(acc[m][nt][0] + b0, 0.f),
                                fmaxf(acc[m][nt][1] + b1, 0.f));
                    *(uint32_t*)(smem + SA + (uint32_t)(rA + 8) * SROW + (uint32_t)c * 2) =
                        pack_h2(fmaxf(acc[m][nt][2] + b0, 0.f),
                                fmaxf(acc[m][nt][3] + b1, 0.f));
                }
            }
        }
        __syncthreads();

        // segment reduce: 16 groups x 8 rows; each thread owns 4 cols -> float4 atomics
        const int* sSeg = (const int*)(smem + (buf ? PSEG1 : PSEG0));
        const int row0 = t * 128;
        const int col4 = tid & 31;          // float4 column group
        const int rbeg = (tid >> 5) * 8;    // 8-row strip
        float4 hv[8];
#pragma unroll
        for (int r = 0; r < 8; r++) {
            uint2 u = *(const uint2*)(smem + SA + (uint32_t)(rbeg + r) * SROW +
                                      (uint32_t)col4 * 8);
            __half2 p0 = *(__half2*)&u.x, p1 = *(__half2*)&u.y;
            float2 f0 = __half22float2(p0), f1 = __half22float2(p1);
            hv[r] = make_float4(f0.x, f0.y, f1.x, f1.y);
        }
        int cur = (row0 + rbeg < nrows) ? sSeg[rbeg] : -1;
        float4 run = make_float4(0.f, 0.f, 0.f, 0.f);
        float cnt = 0.f;
#pragma unroll
        for (int r = 0; r < 8; r++) {
            int s = (row0 + rbeg + r < nrows) ? sSeg[rbeg + r] : -1;
            if (s != cur) {
                if (cur >= 0) {
                    atomicAdd((float4*)(g_segsum + (size_t)cur * D + col4 * 4), run);
                    if (col4 == 0) atomicAdd(&g_cnt[cur], cnt);
                }
                cur = s;
                run = make_float4(0.f, 0.f, 0.f, 0.f);
                cnt = 0.f;
            }
            run.x += hv[r].x; run.y += hv[r].y;
            run.z += hv[r].z; run.w += hv[r].w;
            cnt += 1.f;
        }
        if (cur >= 0) {
            atomicAdd((float4*)(g_segsum + (size_t)cur * D + col4 * 4), run);
            if (col4 == 0) atomicAdd(&g_cnt[cur], cnt);
        }
        __syncthreads();   // SA reads done before next convert overwrites
        buf ^= 1;
    }
}

// ---------------------------------------------------------------------------
// fused small path (1024 threads, 128-row tiles, fp16 2-term)
// ---------------------------------------------------------------------------
__global__ __launch_bounds__(1024, 1) void rho_fused_kernel(
    const __half* __restrict__ W2hi, const __half* __restrict__ W2lo,
    const __half* __restrict__ R1hi, const __half* __restrict__ R1lo,
    const __half* __restrict__ R2hi, const __half* __restrict__ R2lo,
    const float* __restrict__ b2, const float* __restrict__ rb1,
    const float* __restrict__ rb2, float* __restrict__ outp, int nrows)
{
    extern __shared__ __align__(16) char smem[];
    const uint32_t sbase = smem_u32(smem);
    const int tid = threadIdx.x;
    const int wid = tid >> 5, lane = tid & 31;
    const int wm = wid & 7, wn = wid >> 3;
    const int row0 = blockIdx.x * 128;

    float* sB = (float*)(smem + RBIAS);
    float* sCnt = (float*)(smem + RCNT);
    if (tid < D) {
        sB[tid] = b2[tid];
        sB[128 + tid] = rb1[tid];
        sB[256 + tid] = rb2[tid];
    }
    if (tid < 128) {
        int gr = row0 + tid;
        sCnt[tid] = (gr < nrows) ? g_cnt[gr] : 0.f;
    }
    load_W_pair<1024>(smem, W2hi, W2lo, tid);
    __syncthreads();

    // A tile: mean = segsum / max(cnt,1), single fp16
    for (int idx = tid; idx < 128 * 32; idx += 1024) {
        int r = idx >> 5, c4 = idx & 31;
        float4 v = make_float4(0.f, 0.f, 0.f, 0.f);
        int gr = row0 + r;
        if (gr < nrows) {
            v = *(const float4*)(g_segsum + (size_t)gr * D + c4 * 4);
            float s = 1.f / fmaxf(sCnt[r], 1.f);
            v.x *= s; v.y *= s; v.z *= s; v.w *= s;
        }
        uint32_t off = (uint32_t)r * SROW + (uint32_t)c4 * 8;
        *(uint2*)(smem + R_A + off) = make_uint2(pack_h2(v.x, v.y), pack_h2(v.z, v.w));
    }
    __syncthreads();

    const uint32_t aRow = (uint32_t)(wm * 16 + (lane & 15));
    const uint32_t aColB = (uint32_t)((lane >> 4) * 16);
    const uint32_t aBase0 = sbase + R_A + aRow * SROW + aColB;
    const uint32_t bRow = (uint32_t)((lane & 7) + ((lane & 16) ? 8 : 0));
    const uint32_t bColB = (uint32_t)(((lane & 8) ? 8 : 0) * 2);
    const uint32_t bHi0 = sbase + SW_HI + (bRow + (uint32_t)wn * 32u) * SROW + bColB;
    const uint32_t bLo0 = sbase + SW_LO + (bRow + (uint32_t)wn * 32u) * SROW + bColB;

    float acc[4][4];
    // ---- stage 1: u = mean@phiW2 + b2 (zero empty rows) ----
#pragma unroll
    for (int i = 0; i < 4; i++)
#pragma unroll
        for (int j = 0; j < 4; j++) acc[i][j] = 0.f;
    gemm_pass2_16(aBase0, bHi0, bLo0, acc);
    __syncthreads();
    frag_store_A((char*)smem, acc, sB, sCnt, false, true, wm, wn, lane);
    load_W_pair<1024>((char*)smem, R1hi, R1lo, tid);
    __syncthreads();

    // ---- stage 2: v = relu(u@rhoW1 + rb1) ----
#pragma unroll
    for (int i = 0; i < 4; i++)
#pragma unroll
        for (int j = 0; j < 4; j++) acc[i][j] = 0.f;
    gemm_pass2_16(aBase0, bHi0, bLo0, acc);
    __syncthreads();
    frag_store_A((char*)smem, acc, sB + 128, sCnt, true, false, wm, wn, lane);
    load_W_pair<1024>((char*)smem, R2hi, R2lo, tid);
    __syncthreads();

    // ---- stage 3: out = v@rhoW2 + rb2 ----
#pragma unroll
    for (int i = 0; i < 4; i++)
#pragma unroll
        for (int j = 0; j < 4; j++) acc[i][j] = 0.f;
    gemm_pass2_16(aBase0, bHi0, bLo0, acc);
    {
        const int grp = lane >> 2, qp = lane & 3;
        const int rA = wm * 16 + grp;
        int gr0 = row0 + rA, gr1 = row0 + rA + 8;
#pragma unroll
        for (int nt = 0; nt < 4; nt++) {
            int c = wn * 32 + nt * 8 + qp * 2;
            float b0 = sB[256 + c], b1 = sB[256 + c + 1];
            if (gr0 < nrows)
                *(float2*)(outp + (size_t)gr0 * D + c) =
                    make_float2(acc[nt][0] + b0, acc[nt][1] + b1);
            if (gr1 < nrows)
                *(float2*)(outp + (size_t)gr1 * D + c) =
                    make_float2(acc[nt][2] + b0, acc[nt][3] + b1);
        }
    }
}

// ---------------------------------------------------------------------------
extern "C" void kernel_launch(void* const* d_in, const int* in_sizes, int n_in,
                              void* d_out, int out_size)
{
    const float* ins    = (const float*)d_in[0];
    const int*   batch  = (const int*)d_in[1];
    const float* phi_W1 = (const float*)d_in[3];
    const float* phi_b1 = (const float*)d_in[4];
    const float* phi_W2 = (const float*)d_in[5];
    const float* phi_b2 = (const float*)d_in[6];
    const float* rho_W1 = (const float*)d_in[7];
    const float* rho_b1 = (const float*)d_in[8];
    const float* rho_W2 = (const float*)d_in[9];
    const float* rho_b2 = (const float*)d_in[10];
    float* out = (float*)d_out;

    const int N = in_sizes[0] / D;
    const int ntiles = (N + 127) / 128;

    cudaFuncSetAttribute(phi_seg_kernel, cudaFuncAttributeMaxDynamicSharedMemorySize, PHI_SMEM);
    cudaFuncSetAttribute(rho_fused_kernel, cudaFuncAttributeMaxDynamicSharedMemorySize, RHO_SMEM);

    void *p_whi = nullptr, *p_wlo = nullptr;
    cudaGetSymbolAddress(&p_whi, g_Whi);
    cudaGetSymbolAddress(&p_wlo, g_Wlo);
    const __half* Whi = (const __half*)p_whi;
    const __half* Wlo = (const __half*)p_wlo;

    int zgrid = (NSEG * D / 4 + 255) / 256;
    zero_kernel<<<zgrid, 256>>>();
    prep_kernel<<<(4 * D * D + 255) / 256, 256>>>(phi_W1, phi_W2, rho_W1, rho_W2);

    int gphi = 148;
    if (gphi > ntiles) gphi = ntiles;
    phi_seg_kernel<<<gphi, 512, PHI_SMEM>>>(ins, batch,
        Whi + 0 * D * D, Wlo + 0 * D * D, phi_b1, N, ntiles);

    int g2 = (NSEG + 127) / 128;
    rho_fused_kernel<<<g2, 1024, RHO_SMEM>>>(
        Whi + 1 * D * D, Wlo + 1 * D * D,
        Whi + 2 * D * D, Wlo + 2 * D * D,
        Whi + 3 * D * D, Wlo + 3 * D * D,
        phi_b2, rho_b1, rho_b2, out, NSEG);
}

// round 12
// speedup vs baseline: 2.0325x; 1.2914x over previous
#include <cuda_runtime.h>
#include <cuda_fp16.h>
#include <cstdint>

#define D 128
#define NSEG 50000

// ---------------- device scratch ----------------
__device__ __align__(16) float g_segsum[NSEG * D];
__device__ __align__(16) float g_cnt[NSEG];
// transposed weights Wt[n][k] = W[k][n], single fp16, 4 matrices
__device__ __align__(16) __half g_W[4][D * D];

// ---------------- smem layouts (bytes) ----------------
#define SROW 272u
#define SW    0u            // W: 128 rows x 272B
#define SA    34816u        // A: 128 rows x 272B
// phi extras
#define STAGE 69632u        // fp32 A staging, 65536 B
#define PBIAS 135168u
#define PSEG0 135680u
#define PSEG1 136192u
#define PHI_SMEM 136704u
// rho extras
#define RBIAS 69632u        // 3 x 512 B
#define RCNT  71168u        // 512 B
#define RHO_SMEM 71680u

__device__ __forceinline__ uint32_t smem_u32(const void* p) {
    return (uint32_t)__cvta_generic_to_shared(p);
}

#define LDSM_X4(r, addr)                                                      \
    asm volatile("ldmatrix.sync.aligned.m8n8.x4.shared.b16 {%0,%1,%2,%3}, [%4];" \
                 : "=r"((r)[0]), "=r"((r)[1]), "=r"((r)[2]), "=r"((r)[3])     \
                 : "r"(addr))

#define MMA_F16(d, a, b0, b1)                                                 \
    asm volatile("mma.sync.aligned.m16n8k16.row.col.f32.f16.f16.f32 "         \
                 "{%0,%1,%2,%3},{%4,%5,%6,%7},{%8,%9},{%0,%1,%2,%3};"         \
                 : "+f"((d)[0]), "+f"((d)[1]), "+f"((d)[2]), "+f"((d)[3])     \
                 : "r"((a)[0]), "r"((a)[1]), "r"((a)[2]), "r"((a)[3]),        \
                   "r"(b0), "r"(b1))

__device__ __forceinline__ uint32_t pack_h2(float x, float y) {
    __half2 t = __floats2half2_rn(x, y);
    return *(uint32_t*)&t;
}
__device__ __forceinline__ void cp16(uint32_t dst, const void* src, int bytes) {
    asm volatile("cp.async.cg.shared.global [%0], [%1], 16, %2;"
                 :: "r"(dst), "l"(src), "r"(bytes) : "memory");
}
__device__ __forceinline__ void cp_commit() {
    asm volatile("cp.async.commit_group;" ::: "memory");
}
__device__ __forceinline__ void cp_wait0() {
    asm volatile("cp.async.wait_group 0;" ::: "memory");
}

// ---------------------------------------------------------------------------
__global__ void prep_kernel(const float* __restrict__ W0, const float* __restrict__ W1,
                            const float* __restrict__ W2, const float* __restrict__ W3) {
    int i = blockIdx.x * blockDim.x + threadIdx.x;
    if (i >= 4 * D * D) return;
    const float* Ws[4] = {W0, W1, W2, W3};
    int mat = i >> 14;
    int e = i & (D * D - 1);
    int n = e >> 7, k = e & (D - 1);
    g_W[mat][n * D + k] = __float2half_rn(Ws[mat][k * D + n]);
}

__global__ void zero_kernel() {
    int i = blockIdx.x * blockDim.x + threadIdx.x;
    float4 z = make_float4(0.f, 0.f, 0.f, 0.f);
    if (i < NSEG * D / 4) ((float4*)g_segsum)[i] = z;
    if (i < NSEG / 4) ((float4*)g_cnt)[i] = z;
}

// ---------------------------------------------------------------------------
template <int NTHR>
__device__ __forceinline__ void load_W(char* smem, const __half* __restrict__ W,
                                       int tid) {
    for (int idx = tid; idx < 128 * 16; idx += NTHR) {
        int r = idx >> 4, ch = idx & 15;
        *(uint4*)(smem + SW + (uint32_t)r * SROW + (uint32_t)ch * 16) =
            *(const uint4*)(W + r * D + ch * 8);
    }
}

// ======== phi: fp16 1-term, 32x32 warp tile, pipelined (16 warps) ========
__device__ __forceinline__ void gemm_pass1_32(uint32_t aBase, uint32_t bBase,
                                              float (*acc)[4][4]) {
    uint32_t A0[4], A1[4], W0[4], W1[4];
    LDSM_X4(A0, aBase);
    LDSM_X4(A1, aBase + 16u * SROW);
    LDSM_X4(W0, bBase);
    LDSM_X4(W1, bBase + 16u * SROW);
#pragma unroll
    for (int k = 0; k < 8; k++) {
        uint32_t A0n[4], A1n[4], W0n[4], W1n[4];
        if (k < 7) {
            LDSM_X4(A0n, aBase + 32);
            LDSM_X4(A1n, aBase + 16u * SROW + 32);
        }
        MMA_F16(acc[0][0], A0, W0[0], W0[1]);
        MMA_F16(acc[0][1], A0, W0[2], W0[3]);
        MMA_F16(acc[0][2], A0, W1[0], W1[1]);
        MMA_F16(acc[0][3], A0, W1[2], W1[3]);
        if (k < 7) {
            LDSM_X4(W0n, bBase + 32);
            LDSM_X4(W1n, bBase + 16u * SROW + 32);
        }
        MMA_F16(acc[1][0], A1, W0[0], W0[1]);
        MMA_F16(acc[1][1], A1, W0[2], W0[3]);
        MMA_F16(acc[1][2], A1, W1[0], W1[1]);
        MMA_F16(acc[1][3], A1, W1[2], W1[3]);
        if (k < 7) {
#pragma unroll
            for (int i = 0; i < 4; i++) {
                A0[i] = A0n[i]; A1[i] = A1n[i];
                W0[i] = W0n[i]; W1[i] = W1n[i];
            }
            aBase += 32; bBase += 32;
        }
    }
}

// ======== rho: fp16 1-term, 16x32 warp tile, pipelined (32 warps) ========
__device__ __forceinline__ void gemm_pass1_16(uint32_t aBase, uint32_t bBase,
                                              float (*acc)[4]) {
    uint32_t A0[4], W0[4], W1[4];
    LDSM_X4(A0, aBase);
    LDSM_X4(W0, bBase);
    LDSM_X4(W1, bBase + 16u * SROW);
#pragma unroll
    for (int k = 0; k < 8; k++) {
        uint32_t A0n[4], W0n[4], W1n[4];
        if (k < 7) {
            LDSM_X4(A0n, aBase + 32);
            LDSM_X4(W0n, bBase + 32);
            LDSM_X4(W1n, bBase + 16u * SROW + 32);
        }
        MMA_F16(acc[0], A0, W0[0], W0[1]);
        MMA_F16(acc[1], A0, W0[2], W0[3]);
        MMA_F16(acc[2], A0, W1[0], W1[1]);
        MMA_F16(acc[3], A0, W1[2], W1[3]);
        if (k < 7) {
#pragma unroll
            for (int i = 0; i < 4; i++) {
                A0[i] = A0n[i]; W0[i] = W0n[i]; W1[i] = W1n[i];
            }
            aBase += 32; bBase += 32;
        }
    }
}

// rho fragments (+bias, opt relu, opt zero-empty) back to A smem as fp16
__device__ __forceinline__ void frag_store_A(char* smem, float (*acc)[4],
                                             const float* bias, const float* sCnt,
                                             bool relu, bool zeroE,
                                             int wm, int wn, int lane) {
    const int grp = lane >> 2, qp = lane & 3;
    const int rA = wm * 16 + grp;
    bool z0 = zeroE && (sCnt[rA] <= 0.f);
    bool z1 = zeroE && (sCnt[rA + 8] <= 0.f);
#pragma unroll
    for (int nt = 0; nt < 4; nt++) {
        int c = wn * 32 + nt * 8 + qp * 2;
        float b0 = bias[c], b1 = bias[c + 1];
        float x0 = acc[nt][0] + b0, y0 = acc[nt][1] + b1;
        float x1 = acc[nt][2] + b0, y1 = acc[nt][3] + b1;
        if (relu) {
            x0 = fmaxf(x0, 0.f); y0 = fmaxf(y0, 0.f);
            x1 = fmaxf(x1, 0.f); y1 = fmaxf(y1, 0.f);
        }
        if (z0) { x0 = 0.f; y0 = 0.f; }
        if (z1) { x1 = 0.f; y1 = 0.f; }
        uint32_t o0 = (uint32_t)rA * SROW + (uint32_t)c * 2;
        uint32_t o1 = (uint32_t)(rA + 8) * SROW + (uint32_t)c * 2;
        *(uint32_t*)(smem + SA + o0) = pack_h2(x0, y0);
        *(uint32_t*)(smem + SA + o1) = pack_h2(x1, y1);
    }
}

// ---------------------------------------------------------------------------
// PERSISTENT phi kernel: 512 threads, 4x4 grid of 32x32 tiles, fp16 1-term.
// ---------------------------------------------------------------------------
__global__ __launch_bounds__(512, 1) void phi_seg_kernel(
    const float* __restrict__ ins, const int* __restrict__ batch,
    const __half* __restrict__ W, const float* __restrict__ bias,
    int nrows, int ntiles)
{
    extern __shared__ __align__(16) char smem[];
    const uint32_t sbase = smem_u32(smem);
    const int tid = threadIdx.x;
    const int wid = tid >> 5, lane = tid & 31;
    const int wm = wid & 3, wn = wid >> 2;

    // prologue prefetch of first tile
    {
        int t = blockIdx.x;
        if (t < ntiles) {
            long long row0 = (long long)t * 128;
            for (int idx = tid; idx < 4096; idx += 512) {
                int r = idx >> 5, c = idx & 31;
                long long gr = row0 + r;
                cp16(sbase + STAGE + (uint32_t)idx * 16u,
                     ins + gr * D + c * 4, (gr < nrows) ? 16 : 0);
            }
            if (tid < 32) {
                long long r0 = row0 + tid * 4;
                long long rem = (long long)nrows - r0;
                int sz = rem >= 4 ? 16 : (rem > 0 ? (int)rem * 4 : 0);
                cp16(sbase + PSEG0 + (uint32_t)tid * 16u, batch + r0, sz);
            }
        }
        cp_commit();
    }
    load_W<512>(smem, W, tid);
    if (tid < D) ((float*)(smem + PBIAS))[tid] = bias[tid];

    const uint32_t aRow = (uint32_t)(wm * 32 + (lane & 15));
    const uint32_t aColB = (uint32_t)((lane >> 4) * 16);
    const uint32_t aBase0 = sbase + SA + aRow * SROW + aColB;
    const uint32_t bRow = (uint32_t)((lane & 7) + ((lane & 16) ? 8 : 0));
    const uint32_t bColB = (uint32_t)(((lane & 8) ? 8 : 0) * 2);
    const uint32_t bBase0 = sbase + SW + (bRow + (uint32_t)wn * 32u) * SROW + bColB;

    int buf = 0;
    for (int t = blockIdx.x; t < ntiles; t += gridDim.x) {
        cp_wait0();
        __syncthreads();
        // convert staged fp32 -> fp16
        for (int idx = tid; idx < 4096; idx += 512) {
            int r = idx >> 5, c4 = idx & 31;
            float4 v = *(const float4*)(smem + STAGE + (uint32_t)r * 512u + (uint32_t)c4 * 16u);
            uint32_t off = (uint32_t)r * SROW + (uint32_t)c4 * 8;
            *(uint2*)(smem + SA + off) = make_uint2(pack_h2(v.x, v.y), pack_h2(v.z, v.w));
        }
        __syncthreads();   // stage free -> prefetch next tile
        {
            int nt_ = t + gridDim.x;
            if (nt_ < ntiles) {
                long long row0n = (long long)nt_ * 128;
                for (int idx = tid; idx < 4096; idx += 512) {
                    int r = idx >> 5, c = idx & 31;
                    long long gr = row0n + r;
                    cp16(sbase + STAGE + (uint32_t)idx * 16u,
                         ins + gr * D + c * 4, (gr < nrows) ? 16 : 0);
                }
                if (tid < 32) {
                    long long r0 = row0n + tid * 4;
                    long long rem = (long long)nrows - r0;
                    int sz = rem >= 4 ? 16 : (rem > 0 ? (int)rem * 4 : 0);
                    cp16(sbase + (buf ? PSEG0 : PSEG1) + (uint32_t)tid * 16u,
                         batch + r0, sz);
                }
            }
            cp_commit();
        }

        float acc[2][4][4];
#pragma unroll
        for (int m = 0; m < 2; m++)
#pragma unroll
            for (int i = 0; i < 4; i++)
#pragma unroll
                for (int j = 0; j < 4; j++) acc[m][i][j] = 0.f;
        gemm_pass1_32(aBase0, bBase0, acc);
        __syncthreads();   // A buffer reads done

        // h = relu(acc + b) stored fp16 into SA
        const float* sB = (const float*)(smem + PBIAS);
        {
            const int grp = lane >> 2, qp = lane & 3;
#pragma unroll
            for (int m = 0; m < 2; m++) {
                const int rA = wm * 32 + m * 16 + grp;
#pragma unroll
                for (int nt = 0; nt < 4; nt++) {
                    int c = wn * 32 + nt * 8 + qp * 2;
                    float b0 = sB[c], b1 = sB[c + 1];
                    *(uint32_t*)(smem + SA + (uint32_t)rA * SROW + (uint32_t)c * 2) =
                        pack_h2(fmaxf(acc[m][nt][0] + b0, 0.f),
                                fmaxf(acc[m][nt][1] + b1, 0.f));
                    *(uint32_t*)(smem + SA + (uint32_t)(rA + 8) * SROW + (uint32_t)c * 2) =
                        pack_h2(fmaxf(acc[m][nt][2] + b0, 0.f),
                                fmaxf(acc[m][nt][3] + b1, 0.f));
                }
            }
        }
        __syncthreads();

        // segment reduce: 16 groups x 8 rows; each thread owns 4 cols -> float4 atomics
        const int* sSeg = (const int*)(smem + (buf ? PSEG1 : PSEG0));
        const int row0 = t * 128;
        const int col4 = tid & 31;
        const int rbeg = (tid >> 5) * 8;
        float4 hv[8];
#pragma unroll
        for (int r = 0; r < 8; r++) {
            uint2 u = *(const uint2*)(smem + SA + (uint32_t)(rbeg + r) * SROW +
                                      (uint32_t)col4 * 8);
            __half2 p0 = *(__half2*)&u.x, p1 = *(__half2*)&u.y;
            float2 f0 = __half22float2(p0), f1 = __half22float2(p1);
            hv[r] = make_float4(f0.x, f0.y, f1.x, f1.y);
        }
        int cur = (row0 + rbeg < nrows) ? sSeg[rbeg] : -1;
        float4 run = make_float4(0.f, 0.f, 0.f, 0.f);
        float cnt = 0.f;
#pragma unroll
        for (int r = 0; r < 8; r++) {
            int s = (row0 + rbeg + r < nrows) ? sSeg[rbeg + r] : -1;
            if (s != cur) {
                if (cur >= 0) {
                    atomicAdd((float4*)(g_segsum + (size_t)cur * D + col4 * 4), run);
                    if (col4 == 0) atomicAdd(&g_cnt[cur], cnt);
                }
                cur = s;
                run = make_float4(0.f, 0.f, 0.f, 0.f);
                cnt = 0.f;
            }
            run.x += hv[r].x; run.y += hv[r].y;
            run.z += hv[r].z; run.w += hv[r].w;
            cnt += 1.f;
        }
        if (cur >= 0) {
            atomicAdd((float4*)(g_segsum + (size_t)cur * D + col4 * 4), run);
            if (col4 == 0) atomicAdd(&g_cnt[cur], cnt);
        }
        __syncthreads();   // SA reads done before next convert overwrites
        buf ^= 1;
    }
}

// ---------------------------------------------------------------------------
// fused small path (1024 threads, 128-row tiles, fp16 1-term)
// ---------------------------------------------------------------------------
__global__ __launch_bounds__(1024, 1) void rho_fused_kernel(
    const __half* __restrict__ W2, const __half* __restrict__ R1,
    const __half* __restrict__ R2,
    const float* __restrict__ b2, const float* __restrict__ rb1,
    const float* __restrict__ rb2, float* __restrict__ outp, int nrows)
{
    extern __shared__ __align__(16) char smem[];
    const uint32_t sbase = smem_u32(smem);
    const int tid = threadIdx.x;
    const int wid = tid >> 5, lane = tid & 31;
    const int wm = wid & 7, wn = wid >> 3;
    const int row0 = blockIdx.x * 128;

    float* sB = (float*)(smem + RBIAS);
    float* sCnt = (float*)(smem + RCNT);
    if (tid < D) {
        sB[tid] = b2[tid];
        sB[128 + tid] = rb1[tid];
        sB[256 + tid] = rb2[tid];
    }
    if (tid < 128) {
        int gr = row0 + tid;
        sCnt[tid] = (gr < nrows) ? g_cnt[gr] : 0.f;
    }
    load_W<1024>(smem, W2, tid);
    __syncthreads();

    // A tile: mean = segsum / max(cnt,1), fp16
    for (int idx = tid; idx < 128 * 32; idx += 1024) {
        int r = idx >> 5, c4 = idx & 31;
        float4 v = make_float4(0.f, 0.f, 0.f, 0.f);
        int gr = row0 + r;
        if (gr < nrows) {
            v = *(const float4*)(g_segsum + (size_t)gr * D + c4 * 4);
            float s = 1.f / fmaxf(sCnt[r], 1.f);
            v.x *= s; v.y *= s; v.z *= s; v.w *= s;
        }
        uint32_t off = (uint32_t)r * SROW + (uint32_t)c4 * 8;
        *(uint2*)(smem + SA + off) = make_uint2(pack_h2(v.x, v.y), pack_h2(v.z, v.w));
    }
    __syncthreads();

    const uint32_t aRow = (uint32_t)(wm * 16 + (lane & 15));
    const uint32_t aColB = (uint32_t)((lane >> 4) * 16);
    const uint32_t aBase0 = sbase + SA + aRow * SROW + aColB;
    const uint32_t bRow = (uint32_t)((lane & 7) + ((lane & 16) ? 8 : 0));
    const uint32_t bColB = (uint32_t)(((lane & 8) ? 8 : 0) * 2);
    const uint32_t bBase0 = sbase + SW + (bRow + (uint32_t)wn * 32u) * SROW + bColB;

    float acc[4][4];
    // ---- stage 1: u = mean@phiW2 + b2 (zero empty rows) ----
#pragma unroll
    for (int i = 0; i < 4; i++)
#pragma unroll
        for (int j = 0; j < 4; j++) acc[i][j] = 0.f;
    gemm_pass1_16(aBase0, bBase0, acc);
    __syncthreads();
    frag_store_A((char*)smem, acc, sB, sCnt, false, true, wm, wn, lane);
    load_W<1024>((char*)smem, R1, tid);
    __syncthreads();

    // ---- stage 2: v = relu(u@rhoW1 + rb1) ----
#pragma unroll
    for (int i = 0; i < 4; i++)
#pragma unroll
        for (int j = 0; j < 4; j++) acc[i][j] = 0.f;
    gemm_pass1_16(aBase0, bBase0, acc);
    __syncthreads();
    frag_store_A((char*)smem, acc, sB + 128, sCnt, true, false, wm, wn, lane);
    load_W<1024>((char*)smem, R2, tid);
    __syncthreads();

    // ---- stage 3: out = v@rhoW2 + rb2 ----
#pragma unroll
    for (int i = 0; i < 4; i++)
#pragma unroll
        for (int j = 0; j < 4; j++) acc[i][j] = 0.f;
    gemm_pass1_16(aBase0, bBase0, acc);
    {
        const int grp = lane >> 2, qp = lane & 3;
        const int rA = wm * 16 + grp;
        int gr0 = row0 + rA, gr1 = row0 + rA + 8;
#pragma unroll
        for (int nt = 0; nt < 4; nt++) {
            int c = wn * 32 + nt * 8 + qp * 2;
            float b0 = sB[256 + c], b1 = sB[256 + c + 1];
            if (gr0 < nrows)
                *(float2*)(outp + (size_t)gr0 * D + c) =
                    make_float2(acc[nt][0] + b0, acc[nt][1] + b1);
            if (gr1 < nrows)
                *(float2*)(outp + (size_t)gr1 * D + c) =
                    make_float2(acc[nt][2] + b0, acc[nt][3] + b1);
        }
    }
}

// ---------------------------------------------------------------------------
extern "C" void kernel_launch(void* const* d_in, const int* in_sizes, int n_in,
                              void* d_out, int out_size)
{
    const float* ins    = (const float*)d_in[0];
    const int*   batch  = (const int*)d_in[1];
    const float* phi_W1 = (const float*)d_in[3];
    const float* phi_b1 = (const float*)d_in[4];
    const float* phi_W2 = (const float*)d_in[5];
    const float* phi_b2 = (const float*)d_in[6];
    const float* rho_W1 = (const float*)d_in[7];
    const float* rho_b1 = (const float*)d_in[8];
    const float* rho_W2 = (const float*)d_in[9];
    const float* rho_b2 = (const float*)d_in[10];
    float* out = (float*)d_out;

    const int N = in_sizes[0] / D;
    const int ntiles = (N + 127) / 128;

    cudaFuncSetAttribute(phi_seg_kernel, cudaFuncAttributeMaxDynamicSharedMemorySize, PHI_SMEM);
    cudaFuncSetAttribute(rho_fused_kernel, cudaFuncAttributeMaxDynamicSharedMemorySize, RHO_SMEM);

    void* p_w = nullptr;
    cudaGetSymbolAddress(&p_w, g_W);
    const __half* W = (const __half*)p_w;

    int zgrid = (NSEG * D / 4 + 255) / 256;
    zero_kernel<<<zgrid, 256>>>();
    prep_kernel<<<(4 * D * D + 255) / 256, 256>>>(phi_W1, phi_W2, rho_W1, rho_W2);

    int gphi = 148;
    if (gphi > ntiles) gphi = ntiles;
    phi_seg_kernel<<<gphi, 512, PHI_SMEM>>>(ins, batch,
        W + 0 * D * D, phi_b1, N, ntiles);

    int g2 = (NSEG + 127) / 128;
    rho_fused_kernel<<<g2, 1024, RHO_SMEM>>>(
        W + 1 * D * D, W + 2 * D * D, W + 3 * D * D,
        phi_b2, rho_b1, rho_b2, out, NSEG);
}